// round 1
// baseline (speedup 1.0000x reference)
#include <cuda_runtime.h>
#include <math.h>

// Problem constants
#define B_    128
#define F_    1024
#define D_IN  128
#define H1_   512
#define H2_   512
#define E_    256
#define H_    256
#define NSH   5
#define MROWS (B_ * F_)   // 131072

// ---------------- scratch (device globals; no allocation allowed) ----------
__device__ float g_h1[(size_t)MROWS * H1_];   // 268 MB
__device__ float g_h2[(size_t)MROWS * H2_];   // 268 MB
__device__ float g_emb[(size_t)MROWS * E_];   // 134 MB
__device__ float g_qt[B_ * H_];
__device__ float g_ct[B_ * H_];
__device__ float g_att[B_ * E_];

// ---------------- fused GEMM: C[m,n] = act( sum_k A[m,k]*W[n,k] + bias[n] )
// A: [M,K] row-major, W: [N,K] row-major (PyTorch Linear layout), C: [M,N]
// BM=BN=128, BK=16, 256 threads, 8x8 microtile.
template <int ACT>
__global__ __launch_bounds__(256) void gemm_bias_kernel(
    int M, int N, int K,
    const float* __restrict__ A,
    const float* __restrict__ W,
    const float* __restrict__ bias,
    float* __restrict__ C)
{
    __shared__ float As[16][132];   // +4 pad keeps float4 alignment, reduces store conflicts
    __shared__ float Ws[16][132];

    const int tid  = threadIdx.x;
    const int m0   = blockIdx.y * 128;
    const int n0   = blockIdx.x * 128;
    const int trow = tid >> 4;      // 0..15
    const int tcol = tid & 15;      // 0..15

    float acc[8][8];
#pragma unroll
    for (int i = 0; i < 8; i++)
#pragma unroll
        for (int j = 0; j < 8; j++) acc[i][j] = 0.f;

    for (int k0 = 0; k0 < K; k0 += 16) {
        // cooperative load of A-tile (128x16) and W-tile (128x16), coalesced float4
#pragma unroll
        for (int i = 0; i < 2; i++) {
            int idx = tid + i * 256;          // 0..511
            int r   = idx >> 2;               // 0..127
            int c4  = (idx & 3) << 2;         // 0,4,8,12
            float4 va = *reinterpret_cast<const float4*>(
                &A[(size_t)(m0 + r) * K + k0 + c4]);
            As[c4 + 0][r] = va.x; As[c4 + 1][r] = va.y;
            As[c4 + 2][r] = va.z; As[c4 + 3][r] = va.w;
            float4 vw = *reinterpret_cast<const float4*>(
                &W[(size_t)(n0 + r) * K + k0 + c4]);
            Ws[c4 + 0][r] = vw.x; Ws[c4 + 1][r] = vw.y;
            Ws[c4 + 2][r] = vw.z; Ws[c4 + 3][r] = vw.w;
        }
        __syncthreads();

#pragma unroll
        for (int k = 0; k < 16; k++) {
            float a[8], b[8];
            *reinterpret_cast<float4*>(&a[0]) =
                *reinterpret_cast<const float4*>(&As[k][trow * 8]);
            *reinterpret_cast<float4*>(&a[4]) =
                *reinterpret_cast<const float4*>(&As[k][trow * 8 + 4]);
            *reinterpret_cast<float4*>(&b[0]) =
                *reinterpret_cast<const float4*>(&Ws[k][tcol * 8]);
            *reinterpret_cast<float4*>(&b[4]) =
                *reinterpret_cast<const float4*>(&Ws[k][tcol * 8 + 4]);
#pragma unroll
            for (int i = 0; i < 8; i++)
#pragma unroll
                for (int j = 0; j < 8; j++)
                    acc[i][j] = fmaf(a[i], b[j], acc[i][j]);
        }
        __syncthreads();
    }

    // epilogue: bias + optional ReLU, vectorized stores
#pragma unroll
    for (int i = 0; i < 8; i++) {
        int m = m0 + trow * 8 + i;
#pragma unroll
        for (int j = 0; j < 8; j += 4) {
            int n = n0 + tcol * 8 + j;
            float4 v;
            v.x = acc[i][j + 0] + bias[n + 0];
            v.y = acc[i][j + 1] + bias[n + 1];
            v.z = acc[i][j + 2] + bias[n + 2];
            v.w = acc[i][j + 3] + bias[n + 3];
            if (ACT) {
                v.x = fmaxf(v.x, 0.f); v.y = fmaxf(v.y, 0.f);
                v.z = fmaxf(v.z, 0.f); v.w = fmaxf(v.w, 0.f);
            }
            *reinterpret_cast<float4*>(&C[(size_t)m * N + n]) = v;
        }
    }
}

// ---------------- attention: one block per batch ---------------------------
// logit[f] = dot(emb[b,f,:], qt[b,:]); masked -> -1e30; softmax; attended.
__global__ __launch_bounds__(256) void attention_kernel(
    const float* __restrict__ emb, const int* __restrict__ length,
    const float* __restrict__ qt, float* __restrict__ att)
{
    const int b   = blockIdx.x;
    const int tid = threadIdx.x;
    const int warp = tid >> 5, lane = tid & 31;

    __shared__ float s_q[H_];
    __shared__ float s_w[F_];
    __shared__ float s_r[256];

    s_q[tid] = qt[b * H_ + tid];
    __syncthreads();

    const int len = length[b];
    const float* eb = emb + (size_t)b * F_ * E_;

    // logits, warp per row (coalesced 128B row reads)
    for (int f = warp; f < F_; f += 8) {
        const float* row = eb + (size_t)f * E_;
        float d = 0.f;
#pragma unroll
        for (int i = 0; i < 8; i++) {
            int e = lane + 32 * i;
            d = fmaf(row[e], s_q[e], d);
        }
#pragma unroll
        for (int o = 16; o; o >>= 1) d += __shfl_xor_sync(0xffffffffu, d, o);
        if (lane == 0) s_w[f] = (f < len) ? d : -1e30f;
    }
    __syncthreads();

    // block max
    float lm = -INFINITY;
#pragma unroll
    for (int i = 0; i < 4; i++) lm = fmaxf(lm, s_w[tid + i * 256]);
    s_r[tid] = lm;
    __syncthreads();
    for (int s = 128; s > 0; s >>= 1) {
        if (tid < s) s_r[tid] = fmaxf(s_r[tid], s_r[tid + s]);
        __syncthreads();
    }
    const float mx = s_r[0];
    __syncthreads();

    // exp + block sum  (masked entries: exp(-1e30 - mx) == 0, matches jnp.where)
    float ls = 0.f;
#pragma unroll
    for (int i = 0; i < 4; i++) {
        int f = tid + i * 256;
        float w = expf(s_w[f] - mx);
        s_w[f] = w;
        ls += w;
    }
    s_r[tid] = ls;
    __syncthreads();
    for (int s = 128; s > 0; s >>= 1) {
        if (tid < s) s_r[tid] += s_r[tid + s];
        __syncthreads();
    }
    const float inv = 1.f / s_r[0];

    // attended[e] = sum_f w[f] * emb[b,f,e]  (thread per e, coalesced)
    float acc = 0.f;
#pragma unroll 8
    for (int f = 0; f < F_; f++)
        acc = fmaf(s_w[f], eb[(size_t)f * E_ + tid], acc);
    att[b * E_ + tid] = acc * inv;
}

// ---------------- LSTM cell: one block per batch ---------------------------
// gates = x@W_ih.T + b_ih + h@W_hh.T + b_hh ; order i,f,g,o
__global__ __launch_bounds__(256) void lstm_kernel(
    const float* __restrict__ att,
    const float* __restrict__ W_ih, const float* __restrict__ W_hh,
    const float* __restrict__ b_ih, const float* __restrict__ b_hh,
    float* __restrict__ qt, float* __restrict__ ct)
{
    const int b   = blockIdx.x;
    const int tid = threadIdx.x;
    const int warp = tid >> 5, lane = tid & 31;

    __shared__ float s_x[E_];
    __shared__ float s_h[H_];
    __shared__ float s_g[4 * H_];

    s_x[tid] = att[b * E_ + tid];
    s_h[tid] = qt[b * H_ + tid];
    __syncthreads();

    // warp per gate row (coalesced weight reads, L2-resident weights)
    for (int j = warp; j < 4 * H_; j += 8) {
        const float* wi = W_ih + (size_t)j * E_;
        const float* wh = W_hh + (size_t)j * H_;
        float d = 0.f;
#pragma unroll
        for (int i = 0; i < 8; i++) {
            int k = lane + 32 * i;
            d = fmaf(wi[k], s_x[k], d);
            d = fmaf(wh[k], s_h[k], d);
        }
#pragma unroll
        for (int o = 16; o; o >>= 1) d += __shfl_xor_sync(0xffffffffu, d, o);
        if (lane == 0) s_g[j] = d + b_ih[j] + b_hh[j];
    }
    __syncthreads();

    const float gi = 1.f / (1.f + expf(-s_g[tid]));
    const float gf = 1.f / (1.f + expf(-s_g[H_ + tid]));
    const float gg = tanhf(s_g[2 * H_ + tid]);
    const float go = 1.f / (1.f + expf(-s_g[3 * H_ + tid]));

    const float c = gf * ct[b * H_ + tid] + gi * gg;
    const float h = go * tanhf(c);
    ct[b * H_ + tid] = c;
    qt[b * H_ + tid] = h;
}

// ---------------- init / finalize ------------------------------------------
__global__ void init_state_kernel(float* qt, float* ct)
{
    int i = blockIdx.x * blockDim.x + threadIdx.x;
    qt[i] = 0.f;
    ct[i] = 0.f;
}

__global__ void finalize_kernel(const float* __restrict__ att,
                                const float* __restrict__ qt,
                                float* __restrict__ out)
{
    const int b = blockIdx.x;
    const int t = threadIdx.x;   // 512
    out[b * (E_ + H_) + t] = (t < E_) ? att[b * E_ + t] : qt[b * H_ + (t - E_)];
}

// ---------------- launch ----------------------------------------------------
extern "C" void kernel_launch(void* const* d_in, const int* in_sizes, int n_in,
                              void* d_out, int out_size)
{
    const float* state = (const float*)d_in[0];
    const int*   length= (const int*)  d_in[1];
    const float* W1    = (const float*)d_in[2];
    const float* b1    = (const float*)d_in[3];
    const float* W2    = (const float*)d_in[4];
    const float* b2    = (const float*)d_in[5];
    const float* W3    = (const float*)d_in[6];
    const float* b3    = (const float*)d_in[7];
    const float* W_ih  = (const float*)d_in[8];
    const float* W_hh  = (const float*)d_in[9];
    const float* b_ih  = (const float*)d_in[10];
    const float* b_hh  = (const float*)d_in[11];
    float* out = (float*)d_out;

    float *h1, *h2, *emb, *qt, *ct, *att;
    cudaGetSymbolAddress((void**)&h1,  g_h1);
    cudaGetSymbolAddress((void**)&h2,  g_h2);
    cudaGetSymbolAddress((void**)&emb, g_emb);
    cudaGetSymbolAddress((void**)&qt,  g_qt);
    cudaGetSymbolAddress((void**)&ct,  g_ct);
    cudaGetSymbolAddress((void**)&att, g_att);

    init_state_kernel<<<B_ * H_ / 256, 256>>>(qt, ct);

    // embedder MLP
    {
        dim3 g1(H1_ / 128, MROWS / 128);
        gemm_bias_kernel<1><<<g1, 256>>>(MROWS, H1_, D_IN, state, W1, b1, h1);
        dim3 g2(H2_ / 128, MROWS / 128);
        gemm_bias_kernel<1><<<g2, 256>>>(MROWS, H2_, H1_, h1, W2, b2, h2);
        dim3 g3(E_ / 128, MROWS / 128);
        gemm_bias_kernel<0><<<g3, 256>>>(MROWS, E_, H2_, h2, W3, b3, emb);
    }

    // shuffle loop
    for (int s = 0; s < NSH; s++) {
        attention_kernel<<<B_, 256>>>(emb, length, qt, att);
        lstm_kernel<<<B_, 256>>>(att, W_ih, W_hh, b_ih, b_hh, qt, ct);
    }

    finalize_kernel<<<B_, E_ + H_>>>(att, qt, out);
}

// round 3
// speedup vs baseline: 1.1677x; 1.1677x over previous
#include <cuda_runtime.h>
#include <cuda_bf16.h>
#include <math.h>
#include <stdint.h>

// Problem constants
#define B_    128
#define F_    1024
#define D_IN  128
#define H1_   512
#define H2_   512
#define E_    256
#define H_    256
#define NSH   5
#define MROWS (B_ * F_)   // 131072

// ---------------- scratch (device globals; no allocation allowed) ----------
__device__ __nv_bfloat16 g_sth[(size_t)MROWS * D_IN];
__device__ __nv_bfloat16 g_stl[(size_t)MROWS * D_IN];
__device__ __nv_bfloat16 g_h1h[(size_t)MROWS * H1_];
__device__ __nv_bfloat16 g_h1l[(size_t)MROWS * H1_];
__device__ __nv_bfloat16 g_h2h[(size_t)MROWS * H2_];
__device__ __nv_bfloat16 g_h2l[(size_t)MROWS * H2_];
__device__ __nv_bfloat16 g_w1h[H1_ * D_IN], g_w1l[H1_ * D_IN];
__device__ __nv_bfloat16 g_w2h[H2_ * H1_],  g_w2l[H2_ * H1_];
__device__ __nv_bfloat16 g_w3h[E_ * H2_],   g_w3l[E_ * H2_];
__device__ float g_emb[(size_t)MROWS * E_];   // 134 MB
__device__ float g_qt[B_ * H_];
__device__ float g_ct[B_ * H_];
__device__ float g_att[B_ * E_];

// ===================== low-level helpers ===================================
__device__ __forceinline__ uint32_t smem_u32(const void* p) {
    uint32_t a;
    asm("{ .reg .u64 t; cvta.to.shared.u64 t, %1; cvt.u32.u64 %0, t; }"
        : "=r"(a) : "l"(p));
    return a;
}

__device__ __forceinline__ void cp_async16(uint32_t dst, const void* src) {
    asm volatile("cp.async.cg.shared.global [%0], [%1], 16;\n"
                 :: "r"(dst), "l"(src));
}
#define CP_COMMIT() asm volatile("cp.async.commit_group;\n" ::: "memory")
#define CP_WAIT1()  asm volatile("cp.async.wait_group 1;\n" ::: "memory")
#define CP_WAIT0()  asm volatile("cp.async.wait_group 0;\n" ::: "memory")

__device__ __forceinline__ void ldsm4(uint32_t* r, uint32_t addr) {
    asm volatile("ldmatrix.sync.aligned.m8n8.x4.shared.b16 {%0,%1,%2,%3}, [%4];\n"
                 : "=r"(r[0]), "=r"(r[1]), "=r"(r[2]), "=r"(r[3]) : "r"(addr));
}

__device__ __forceinline__ void mma16816(float* d, const uint32_t* a, const uint32_t* b) {
    asm volatile(
        "mma.sync.aligned.m16n8k16.row.col.f32.bf16.bf16.f32 "
        "{%0,%1,%2,%3}, {%4,%5,%6,%7}, {%8,%9}, {%0,%1,%2,%3};\n"
        : "+f"(d[0]), "+f"(d[1]), "+f"(d[2]), "+f"(d[3])
        : "r"(a[0]), "r"(a[1]), "r"(a[2]), "r"(a[3]), "r"(b[0]), "r"(b[1]));
}

__device__ __forceinline__ uint32_t pack_bf2(__nv_bfloat16 a, __nv_bfloat16 b) {
    __nv_bfloat162 t = __halves2bfloat162(a, b);
    return reinterpret_cast<uint32_t&>(t);
}

// =================== HMMA GEMM: C = act(A @ W^T + bias) =====================
// A given as bf16 hi/lo pair [M,K]; W as bf16 hi/lo pair [N,K].
// D = Ah*Wh + Ah*Wl + Al*Wh accumulated in fp32 (error ~2^-16).
// CTA tile 128x128, 8 warps (2x4), warp tile 64x32, BK=32, double-buffered
// cp.async. SMEM rows padded to 80B -> conflict-free ldmatrix.
static constexpr int TILE_B   = 128 * 80;          // 10240 B per operand tile
static constexpr int STAGE_B  = 4 * TILE_B;        // Ah|Al|Wh|Wl = 40960 B
static constexpr int GEMM_SM  = 2 * STAGE_B;       // 81920 B

template <int ACT, int OUT_BF>
__global__ __launch_bounds__(256, 1) void gemm_mma_kernel(
    int M, int N, int K,
    const __nv_bfloat16* __restrict__ Ah, const __nv_bfloat16* __restrict__ Al,
    const __nv_bfloat16* __restrict__ Wh, const __nv_bfloat16* __restrict__ Wl,
    const float* __restrict__ bias,
    float* __restrict__ C,
    __nv_bfloat16* __restrict__ Ch, __nv_bfloat16* __restrict__ Cl)
{
    extern __shared__ char smem[];
    const uint32_t sbase = smem_u32(smem);
    const int tid  = threadIdx.x;
    const int lane = tid & 31;
    const int wid  = tid >> 5;
    const int m0 = blockIdx.y * 128;
    const int n0 = blockIdx.x * 128;
    const int wm = (wid & 1) * 64;     // warp m-offset
    const int wn = (wid >> 1) * 32;    // warp n-offset

    float acc[4][4][4];
#pragma unroll
    for (int i = 0; i < 4; i++)
#pragma unroll
        for (int j = 0; j < 4; j++)
#pragma unroll
            for (int k = 0; k < 4; k++) acc[i][j][k] = 0.f;

    // per-thread cp.async descriptors (8 x 16B chunks per stage)
    const __nv_bfloat16* gsrc[8];
    uint32_t sdst[8];
#pragma unroll
    for (int i = 0; i < 8; i++) {
        int id = tid + i * 256;          // 0..2047
        int t  = id >> 9;                // operand tile 0..3
        int r  = (id >> 2) & 127;        // row
        int c  = id & 3;                 // 16B chunk in row
        const __nv_bfloat16* bp = (t == 0) ? Ah : (t == 1) ? Al : (t == 2) ? Wh : Wl;
        int row = ((t < 2) ? m0 : n0) + r;
        gsrc[i] = bp + (size_t)row * K + c * 8;
        sdst[i] = sbase + t * TILE_B + r * 80 + c * 16;
    }

    // ldmatrix per-lane offsets (relative to stage base)
    uint32_t aoff[4], boff[2];
#pragma unroll
    for (int am = 0; am < 4; am++)
        aoff[am] = (uint32_t)((wm + am * 16 + (lane & 15)) * 80 + (lane >> 4) * 16);
#pragma unroll
    for (int pb = 0; pb < 2; pb++)
        boff[pb] = (uint32_t)((wn + pb * 16 + (lane & 7) + ((lane >> 1) & 8)) * 80
                              + ((lane >> 3) & 1) * 16);

    const int NC = K >> 5;   // chunks of 32

    // prologue: chunk 0 -> stage 0
#pragma unroll
    for (int i = 0; i < 8; i++) cp_async16(sdst[i], gsrc[i]);
    CP_COMMIT();

    for (int cc = 0; cc < NC; cc++) {
        if (cc + 1 < NC) {
            const uint32_t so = ((cc + 1) & 1) * STAGE_B;
            const int k1 = (cc + 1) * 32;
#pragma unroll
            for (int i = 0; i < 8; i++) cp_async16(sdst[i] + so, gsrc[i] + k1);
            CP_COMMIT();
            CP_WAIT1();
        } else {
            CP_WAIT0();
        }
        __syncthreads();

        const uint32_t st = sbase + (cc & 1) * STAGE_B;
#pragma unroll
        for (int s = 0; s < 2; s++) {
            uint32_t ah[4][4], alr[4][4], bh[4][2], blr[4][2];
#pragma unroll
            for (int am = 0; am < 4; am++) {
                ldsm4(ah[am],  st + aoff[am] + s * 32);
                ldsm4(alr[am], st + TILE_B + aoff[am] + s * 32);
            }
#pragma unroll
            for (int pb = 0; pb < 2; pb++) {
                uint32_t r[4];
                ldsm4(r, st + 2 * TILE_B + boff[pb] + s * 32);
                bh[2 * pb][0] = r[0]; bh[2 * pb][1] = r[1];
                bh[2 * pb + 1][0] = r[2]; bh[2 * pb + 1][1] = r[3];
                ldsm4(r, st + 3 * TILE_B + boff[pb] + s * 32);
                blr[2 * pb][0] = r[0]; blr[2 * pb][1] = r[1];
                blr[2 * pb + 1][0] = r[2]; blr[2 * pb + 1][1] = r[3];
            }
#pragma unroll
            for (int am = 0; am < 4; am++)
#pragma unroll
                for (int an = 0; an < 4; an++) {
                    mma16816(acc[am][an], ah[am],  bh[an]);
                    mma16816(acc[am][an], ah[am],  blr[an]);
                    mma16816(acc[am][an], alr[am], bh[an]);
                }
        }
        __syncthreads();
    }

    // epilogue: bias (+ReLU), store fp32 or bf16 hi/lo
#pragma unroll
    for (int am = 0; am < 4; am++) {
        const int r0 = m0 + wm + am * 16 + (lane >> 2);
        const int r1 = r0 + 8;
#pragma unroll
        for (int an = 0; an < 4; an++) {
            const int col = n0 + wn + an * 8 + ((lane & 3) << 1);
            const float bz0 = __ldg(&bias[col]);
            const float bz1 = __ldg(&bias[col + 1]);
            float v00 = acc[am][an][0] + bz0;
            float v01 = acc[am][an][1] + bz1;
            float v10 = acc[am][an][2] + bz0;
            float v11 = acc[am][an][3] + bz1;
            if (ACT) {
                v00 = fmaxf(v00, 0.f); v01 = fmaxf(v01, 0.f);
                v10 = fmaxf(v10, 0.f); v11 = fmaxf(v11, 0.f);
            }
            if (OUT_BF) {
                __nv_bfloat16 h00 = __float2bfloat16(v00), h01 = __float2bfloat16(v01);
                __nv_bfloat16 h10 = __float2bfloat16(v10), h11 = __float2bfloat16(v11);
                __nv_bfloat16 l00 = __float2bfloat16(v00 - __bfloat162float(h00));
                __nv_bfloat16 l01 = __float2bfloat16(v01 - __bfloat162float(h01));
                __nv_bfloat16 l10 = __float2bfloat16(v10 - __bfloat162float(h10));
                __nv_bfloat16 l11 = __float2bfloat16(v11 - __bfloat162float(h11));
                *reinterpret_cast<uint32_t*>(&Ch[(size_t)r0 * N + col]) = pack_bf2(h00, h01);
                *reinterpret_cast<uint32_t*>(&Cl[(size_t)r0 * N + col]) = pack_bf2(l00, l01);
                *reinterpret_cast<uint32_t*>(&Ch[(size_t)r1 * N + col]) = pack_bf2(h10, h11);
                *reinterpret_cast<uint32_t*>(&Cl[(size_t)r1 * N + col]) = pack_bf2(l10, l11);
            } else {
                *reinterpret_cast<float2*>(&C[(size_t)r0 * N + col]) = make_float2(v00, v01);
                *reinterpret_cast<float2*>(&C[(size_t)r1 * N + col]) = make_float2(v10, v11);
            }
        }
    }
}

// ---------------- fp32 -> bf16 hi/lo split ---------------------------------
__global__ __launch_bounds__(256) void split_kernel(
    const float* __restrict__ src,
    __nv_bfloat16* __restrict__ hi, __nv_bfloat16* __restrict__ lo, int n)
{
    int i = (blockIdx.x * 256 + threadIdx.x) * 4;
    if (i >= n) return;
    float4 v = *reinterpret_cast<const float4*>(src + i);
    __nv_bfloat16 h0 = __float2bfloat16(v.x), h1 = __float2bfloat16(v.y);
    __nv_bfloat16 h2 = __float2bfloat16(v.z), h3 = __float2bfloat16(v.w);
    __nv_bfloat16 l0 = __float2bfloat16(v.x - __bfloat162float(h0));
    __nv_bfloat16 l1 = __float2bfloat16(v.y - __bfloat162float(h1));
    __nv_bfloat16 l2 = __float2bfloat16(v.z - __bfloat162float(h2));
    __nv_bfloat16 l3 = __float2bfloat16(v.w - __bfloat162float(h3));
    *reinterpret_cast<uint2*>(&hi[i]) = make_uint2(pack_bf2(h0, h1), pack_bf2(h2, h3));
    *reinterpret_cast<uint2*>(&lo[i]) = make_uint2(pack_bf2(l0, l1), pack_bf2(l2, l3));
}

// ---------------- attention: one block per batch, 512 threads --------------
__global__ __launch_bounds__(512) void attention_kernel(
    const float* __restrict__ emb, const int* __restrict__ length,
    const float* __restrict__ qt, float* __restrict__ att)
{
    const int b    = blockIdx.x;
    const int tid  = threadIdx.x;
    const int warp = tid >> 5, lane = tid & 31;

    __shared__ float s_q[H_];
    __shared__ float s_w[F_];
    __shared__ float s_part[16][E_];
    __shared__ float s_red[512];

    if (tid < H_) s_q[tid] = qt[b * H_ + tid];
    __syncthreads();

    const int len = length[b];
    const float* eb = emb + (size_t)b * F_ * E_;

    // logits: warp per row, 16 warps
    for (int f = warp; f < F_; f += 16) {
        const float* row = eb + (size_t)f * E_;
        float d = 0.f;
#pragma unroll
        for (int i = 0; i < 8; i++) {
            int e = lane + 32 * i;
            d = fmaf(row[e], s_q[e], d);
        }
#pragma unroll
        for (int o = 16; o; o >>= 1) d += __shfl_xor_sync(0xffffffffu, d, o);
        if (lane == 0) s_w[f] = (f < len) ? d : -1e30f;
    }
    __syncthreads();

    // block max
    float lm = fmaxf(s_w[tid], s_w[tid + 512]);
    s_red[tid] = lm;
    __syncthreads();
    for (int s = 256; s > 0; s >>= 1) {
        if (tid < s) s_red[tid] = fmaxf(s_red[tid], s_red[tid + s]);
        __syncthreads();
    }
    const float mx = s_red[0];
    __syncthreads();

    // exp + sum (masked entries underflow to exactly 0, matching jnp.where)
    float e0 = expf(s_w[tid] - mx);
    float e1 = expf(s_w[tid + 512] - mx);
    s_w[tid] = e0;
    s_w[tid + 512] = e1;
    s_red[tid] = e0 + e1;
    __syncthreads();
    for (int s = 256; s > 0; s >>= 1) {
        if (tid < s) s_red[tid] += s_red[tid + s];
        __syncthreads();
    }
    const float inv = 1.f / s_red[0];
    __syncthreads();

    // attended: warp w covers f in [w*64, (w+1)*64), 8 e-regs per thread
    float acc[8];
#pragma unroll
    for (int i = 0; i < 8; i++) acc[i] = 0.f;
    const int fb = warp * 64;
#pragma unroll 4
    for (int ff = 0; ff < 64; ff++) {
        int f = fb + ff;
        float wf = s_w[f];
        const float* row = eb + (size_t)f * E_;
#pragma unroll
        for (int i = 0; i < 8; i++)
            acc[i] = fmaf(wf, row[lane + 32 * i], acc[i]);
    }
#pragma unroll
    for (int i = 0; i < 8; i++) s_part[warp][lane + 32 * i] = acc[i];
    __syncthreads();

    if (tid < E_) {
        float s = 0.f;
#pragma unroll
        for (int w = 0; w < 16; w++) s += s_part[w][tid];
        att[b * E_ + tid] = s * inv;
    }
}

// ---------------- LSTM cell: one block per batch ---------------------------
__global__ __launch_bounds__(256) void lstm_kernel(
    const float* __restrict__ att,
    const float* __restrict__ W_ih, const float* __restrict__ W_hh,
    const float* __restrict__ b_ih, const float* __restrict__ b_hh,
    float* __restrict__ qt, float* __restrict__ ct)
{
    const int b   = blockIdx.x;
    const int tid = threadIdx.x;
    const int warp = tid >> 5, lane = tid & 31;

    __shared__ float s_x[E_];
    __shared__ float s_h[H_];
    __shared__ float s_g[4 * H_];

    s_x[tid] = att[b * E_ + tid];
    s_h[tid] = qt[b * H_ + tid];
    __syncthreads();

    for (int j = warp; j < 4 * H_; j += 8) {
        const float* wi = W_ih + (size_t)j * E_;
        const float* wh = W_hh + (size_t)j * H_;
        float d = 0.f;
#pragma unroll
        for (int i = 0; i < 8; i++) {
            int k = lane + 32 * i;
            d = fmaf(wi[k], s_x[k], d);
            d = fmaf(wh[k], s_h[k], d);
        }
#pragma unroll
        for (int o = 16; o; o >>= 1) d += __shfl_xor_sync(0xffffffffu, d, o);
        if (lane == 0) s_g[j] = d + b_ih[j] + b_hh[j];
    }
    __syncthreads();

    const float gi = 1.f / (1.f + expf(-s_g[tid]));
    const float gf = 1.f / (1.f + expf(-s_g[H_ + tid]));
    const float gg = tanhf(s_g[2 * H_ + tid]);
    const float go = 1.f / (1.f + expf(-s_g[3 * H_ + tid]));

    const float c = gf * ct[b * H_ + tid] + gi * gg;
    const float h = go * tanhf(c);
    ct[b * H_ + tid] = c;
    qt[b * H_ + tid] = h;
}

// ---------------- init / finalize ------------------------------------------
__global__ void init_state_kernel(float* qt, float* ct)
{
    int i = blockIdx.x * blockDim.x + threadIdx.x;
    qt[i] = 0.f;
    ct[i] = 0.f;
}

__global__ void finalize_kernel(const float* __restrict__ att,
                                const float* __restrict__ qt,
                                float* __restrict__ out)
{
    const int b = blockIdx.x;
    const int t = threadIdx.x;   // 512
    out[b * (E_ + H_) + t] = (t < E_) ? att[b * E_ + t] : qt[b * H_ + (t - E_)];
}

// ---------------- launch ----------------------------------------------------
extern "C" void kernel_launch(void* const* d_in, const int* in_sizes, int n_in,
                              void* d_out, int out_size)
{
    const float* state = (const float*)d_in[0];
    const int*   length= (const int*)  d_in[1];
    const float* W1    = (const float*)d_in[2];
    const float* b1    = (const float*)d_in[3];
    const float* W2    = (const float*)d_in[4];
    const float* b2    = (const float*)d_in[5];
    const float* W3    = (const float*)d_in[6];
    const float* b3    = (const float*)d_in[7];
    const float* W_ih  = (const float*)d_in[8];
    const float* W_hh  = (const float*)d_in[9];
    const float* b_ih  = (const float*)d_in[10];
    const float* b_hh  = (const float*)d_in[11];
    float* out = (float*)d_out;

    __nv_bfloat16 *sth, *stl, *h1h, *h1l, *h2h, *h2l;
    __nv_bfloat16 *w1h, *w1l, *w2h, *w2l, *w3h, *w3l;
    float *emb, *qt, *ct, *att;
    cudaGetSymbolAddress((void**)&sth, g_sth);
    cudaGetSymbolAddress((void**)&stl, g_stl);
    cudaGetSymbolAddress((void**)&h1h, g_h1h);
    cudaGetSymbolAddress((void**)&h1l, g_h1l);
    cudaGetSymbolAddress((void**)&h2h, g_h2h);
    cudaGetSymbolAddress((void**)&h2l, g_h2l);
    cudaGetSymbolAddress((void**)&w1h, g_w1h);
    cudaGetSymbolAddress((void**)&w1l, g_w1l);
    cudaGetSymbolAddress((void**)&w2h, g_w2h);
    cudaGetSymbolAddress((void**)&w2l, g_w2l);
    cudaGetSymbolAddress((void**)&w3h, g_w3h);
    cudaGetSymbolAddress((void**)&w3l, g_w3l);
    cudaGetSymbolAddress((void**)&emb, g_emb);
    cudaGetSymbolAddress((void**)&qt,  g_qt);
    cudaGetSymbolAddress((void**)&ct,  g_ct);
    cudaGetSymbolAddress((void**)&att, g_att);

    cudaFuncSetAttribute(gemm_mma_kernel<1, 1>,
                         cudaFuncAttributeMaxDynamicSharedMemorySize, GEMM_SM);
    cudaFuncSetAttribute(gemm_mma_kernel<0, 0>,
                         cudaFuncAttributeMaxDynamicSharedMemorySize, GEMM_SM);

    init_state_kernel<<<B_ * H_ / 256, 256>>>(qt, ct);

    // hi/lo splits of inputs and weights
    split_kernel<<<(MROWS * D_IN) / 1024, 256>>>(state, sth, stl, MROWS * D_IN);
    split_kernel<<<(H1_ * D_IN) / 1024, 256>>>(W1, w1h, w1l, H1_ * D_IN);
    split_kernel<<<(H2_ * H1_) / 1024, 256>>>(W2, w2h, w2l, H2_ * H1_);
    split_kernel<<<(E_ * H2_) / 1024, 256>>>(W3, w3h, w3l, E_ * H2_);

    // embedder MLP on HMMA tensor cores
    {
        dim3 g1(H1_ / 128, MROWS / 128);
        gemm_mma_kernel<1, 1><<<g1, 256, GEMM_SM>>>(
            MROWS, H1_, D_IN, sth, stl, w1h, w1l, b1, nullptr, h1h, h1l);
        dim3 g2(H2_ / 128, MROWS / 128);
        gemm_mma_kernel<1, 1><<<g2, 256, GEMM_SM>>>(
            MROWS, H2_, H1_, h1h, h1l, w2h, w2l, b2, nullptr, h2h, h2l);
        dim3 g3(E_ / 128, MROWS / 128);
        gemm_mma_kernel<0, 0><<<g3, 256, GEMM_SM>>>(
            MROWS, E_, H2_, h2h, h2l, w3h, w3l, b3, emb, nullptr, nullptr);
    }

    // shuffle loop
    for (int s = 0; s < NSH; s++) {
        attention_kernel<<<B_, 512>>>(emb, length, qt, att);
        lstm_kernel<<<B_, 256>>>(att, W_ih, W_hh, b_ih, b_hh, qt, ct);
    }

    finalize_kernel<<<B_, E_ + H_>>>(att, qt, out);
}

// round 4
// speedup vs baseline: 3.1578x; 2.7043x over previous
#include <cuda_runtime.h>
#include <cuda_bf16.h>
#include <math.h>
#include <stdint.h>

// Problem constants
#define B_    128
#define F_    1024
#define D_IN  128
#define H1_   512
#define H2_   512
#define E_    256
#define H_    256
#define NSH   5
#define MROWS (B_ * F_)   // 131072

// ---------------- scratch (device globals; no allocation allowed) ----------
__device__ __nv_bfloat16 g_sth[(size_t)MROWS * D_IN];
__device__ __nv_bfloat16 g_stl[(size_t)MROWS * D_IN];
__device__ __nv_bfloat16 g_h1h[(size_t)MROWS * H1_];
__device__ __nv_bfloat16 g_h1l[(size_t)MROWS * H1_];
__device__ __nv_bfloat16 g_h2h[(size_t)MROWS * H2_];
__device__ __nv_bfloat16 g_h2l[(size_t)MROWS * H2_];
__device__ __nv_bfloat16 g_w1h[H1_ * D_IN], g_w1l[H1_ * D_IN];
__device__ __nv_bfloat16 g_w2h[H2_ * H1_],  g_w2l[H2_ * H1_];
__device__ __nv_bfloat16 g_w3h[E_ * H2_],   g_w3l[E_ * H2_];
__device__ float g_emb[(size_t)MROWS * E_];   // 134 MB

// ===================== low-level helpers ===================================
__device__ __forceinline__ uint32_t smem_u32(const void* p) {
    uint32_t a;
    asm("{ .reg .u64 t; cvta.to.shared.u64 t, %1; cvt.u32.u64 %0, t; }"
        : "=r"(a) : "l"(p));
    return a;
}

__device__ __forceinline__ void cp_async16(uint32_t dst, const void* src) {
    asm volatile("cp.async.cg.shared.global [%0], [%1], 16;\n"
                 :: "r"(dst), "l"(src));
}
#define CP_COMMIT() asm volatile("cp.async.commit_group;\n" ::: "memory")
#define CP_WAIT1()  asm volatile("cp.async.wait_group 1;\n" ::: "memory")
#define CP_WAIT0()  asm volatile("cp.async.wait_group 0;\n" ::: "memory")

__device__ __forceinline__ void ldsm4(uint32_t* r, uint32_t addr) {
    asm volatile("ldmatrix.sync.aligned.m8n8.x4.shared.b16 {%0,%1,%2,%3}, [%4];\n"
                 : "=r"(r[0]), "=r"(r[1]), "=r"(r[2]), "=r"(r[3]) : "r"(addr));
}

__device__ __forceinline__ void mma16816(float* d, const uint32_t* a, const uint32_t* b) {
    asm volatile(
        "mma.sync.aligned.m16n8k16.row.col.f32.bf16.bf16.f32 "
        "{%0,%1,%2,%3}, {%4,%5,%6,%7}, {%8,%9}, {%0,%1,%2,%3};\n"
        : "+f"(d[0]), "+f"(d[1]), "+f"(d[2]), "+f"(d[3])
        : "r"(a[0]), "r"(a[1]), "r"(a[2]), "r"(a[3]), "r"(b[0]), "r"(b[1]));
}

__device__ __forceinline__ uint32_t pack_bf2(__nv_bfloat16 a, __nv_bfloat16 b) {
    __nv_bfloat162 t = __halves2bfloat162(a, b);
    return reinterpret_cast<uint32_t&>(t);
}

// =================== HMMA GEMM: C = act(A @ W^T + bias) =====================
// A as bf16 hi/lo [M,K]; W as bf16 hi/lo [N,K]. D = Ah*Wh + Al*Wh + Ah*Wl.
// CTA tile 128x128, 8 warps (2x4), warp tile 64x32, BK=32, 2-stage cp.async,
// 2 CTAs/SM. SMEM rows padded to 80B -> conflict-free ldmatrix.
static constexpr int TILE_B   = 128 * 80;          // 10240 B per operand tile
static constexpr int STAGE_B  = 4 * TILE_B;        // Ah|Al|Wh|Wl = 40960 B
static constexpr int GEMM_SM  = 2 * STAGE_B;       // 81920 B

template <int ACT, int OUT_BF>
__global__ __launch_bounds__(256, 2) void gemm_mma_kernel(
    int M, int N, int K,
    const __nv_bfloat16* __restrict__ Ah, const __nv_bfloat16* __restrict__ Al,
    const __nv_bfloat16* __restrict__ Wh, const __nv_bfloat16* __restrict__ Wl,
    const float* __restrict__ bias,
    float* __restrict__ C,
    __nv_bfloat16* __restrict__ Ch, __nv_bfloat16* __restrict__ Cl)
{
    extern __shared__ char smem[];
    const uint32_t sbase = smem_u32(smem);
    const int tid  = threadIdx.x;
    const int lane = tid & 31;
    const int wid  = tid >> 5;
    const int m0 = blockIdx.y * 128;
    const int n0 = blockIdx.x * 128;
    const int wm = (wid & 1) * 64;     // warp m-offset
    const int wn = (wid >> 1) * 32;    // warp n-offset

    float acc[4][4][4];
#pragma unroll
    for (int i = 0; i < 4; i++)
#pragma unroll
        for (int j = 0; j < 4; j++)
#pragma unroll
            for (int k = 0; k < 4; k++) acc[i][j][k] = 0.f;

    // per-thread cp.async geometry: i -> tile i/2, row (i&1)*64 + tid/4, chunk tid&3
    const int prow = tid >> 2;
    const int pch  = (tid & 3) * 8;
    const uint32_t sd_base = sbase + prow * 80 + pch * 2;

    // ldmatrix per-lane offsets (relative to stage base)
    uint32_t aoff[4], boff[2];
#pragma unroll
    for (int am = 0; am < 4; am++)
        aoff[am] = (uint32_t)((wm + am * 16 + (lane & 15)) * 80 + (lane >> 4) * 16);
#pragma unroll
    for (int pb = 0; pb < 2; pb++)
        boff[pb] = (uint32_t)((wn + pb * 16 + (lane & 7) + ((lane >> 1) & 8)) * 80
                              + ((lane >> 3) & 1) * 16);

    const int NC = K >> 5;   // chunks of 32

    // prefetch a chunk into stage st
    auto prefetch = [&](int cc, int st) {
        const uint32_t so = sd_base + st * STAGE_B;
        const int kk = cc * 32 + pch;
#pragma unroll
        for (int i = 0; i < 8; i++) {
            const __nv_bfloat16* bp = (i < 2) ? Ah : (i < 4) ? Al : (i < 6) ? Wh : Wl;
            const int rb = ((i < 4) ? m0 : n0) + (i & 1) * 64 + prow;
            cp_async16(so + (i >> 1) * TILE_B + (i & 1) * 64 * 80,
                       bp + (size_t)rb * K + kk);
        }
        CP_COMMIT();
    };

    prefetch(0, 0);

    for (int cc = 0; cc < NC; cc++) {
        if (cc + 1 < NC) { prefetch(cc + 1, (cc + 1) & 1); CP_WAIT1(); }
        else             { CP_WAIT0(); }
        __syncthreads();

        const uint32_t st = sbase + (cc & 1) * STAGE_B;
#pragma unroll
        for (int s = 0; s < 2; s++) {
            uint32_t ah[4][4];
#pragma unroll
            for (int am = 0; am < 4; am++) ldsm4(ah[am], st + aoff[am] + s * 32);
            uint32_t b0[4][2];
#pragma unroll
            for (int pb = 0; pb < 2; pb++) {
                uint32_t r[4];
                ldsm4(r, st + 2 * TILE_B + boff[pb] + s * 32);
                b0[2 * pb][0] = r[0]; b0[2 * pb][1] = r[1];
                b0[2 * pb + 1][0] = r[2]; b0[2 * pb + 1][1] = r[3];
            }
#pragma unroll
            for (int am = 0; am < 4; am++)
#pragma unroll
                for (int an = 0; an < 4; an++) mma16816(acc[am][an], ah[am], b0[an]);

            {
                uint32_t al[4][4];
#pragma unroll
                for (int am = 0; am < 4; am++) ldsm4(al[am], st + TILE_B + aoff[am] + s * 32);
#pragma unroll
                for (int am = 0; am < 4; am++)
#pragma unroll
                    for (int an = 0; an < 4; an++) mma16816(acc[am][an], al[am], b0[an]);
            }
            {
                uint32_t b1[4][2];
#pragma unroll
                for (int pb = 0; pb < 2; pb++) {
                    uint32_t r[4];
                    ldsm4(r, st + 3 * TILE_B + boff[pb] + s * 32);
                    b1[2 * pb][0] = r[0]; b1[2 * pb][1] = r[1];
                    b1[2 * pb + 1][0] = r[2]; b1[2 * pb + 1][1] = r[3];
                }
#pragma unroll
                for (int am = 0; am < 4; am++)
#pragma unroll
                    for (int an = 0; an < 4; an++) mma16816(acc[am][an], ah[am], b1[an]);
            }
        }
        __syncthreads();
    }

    // epilogue: bias (+ReLU), store fp32 or bf16 hi/lo
#pragma unroll
    for (int am = 0; am < 4; am++) {
        const int r0 = m0 + wm + am * 16 + (lane >> 2);
        const int r1 = r0 + 8;
#pragma unroll
        for (int an = 0; an < 4; an++) {
            const int col = n0 + wn + an * 8 + ((lane & 3) << 1);
            const float bz0 = __ldg(&bias[col]);
            const float bz1 = __ldg(&bias[col + 1]);
            float v00 = acc[am][an][0] + bz0;
            float v01 = acc[am][an][1] + bz1;
            float v10 = acc[am][an][2] + bz0;
            float v11 = acc[am][an][3] + bz1;
            if (ACT) {
                v00 = fmaxf(v00, 0.f); v01 = fmaxf(v01, 0.f);
                v10 = fmaxf(v10, 0.f); v11 = fmaxf(v11, 0.f);
            }
            if (OUT_BF) {
                __nv_bfloat16 h00 = __float2bfloat16(v00), h01 = __float2bfloat16(v01);
                __nv_bfloat16 h10 = __float2bfloat16(v10), h11 = __float2bfloat16(v11);
                __nv_bfloat16 l00 = __float2bfloat16(v00 - __bfloat162float(h00));
                __nv_bfloat16 l01 = __float2bfloat16(v01 - __bfloat162float(h01));
                __nv_bfloat16 l10 = __float2bfloat16(v10 - __bfloat162float(h10));
                __nv_bfloat16 l11 = __float2bfloat16(v11 - __bfloat162float(h11));
                *reinterpret_cast<uint32_t*>(&Ch[(size_t)r0 * N + col]) = pack_bf2(h00, h01);
                *reinterpret_cast<uint32_t*>(&Cl[(size_t)r0 * N + col]) = pack_bf2(l00, l01);
                *reinterpret_cast<uint32_t*>(&Ch[(size_t)r1 * N + col]) = pack_bf2(h10, h11);
                *reinterpret_cast<uint32_t*>(&Cl[(size_t)r1 * N + col]) = pack_bf2(l10, l11);
            } else {
                *reinterpret_cast<float2*>(&C[(size_t)r0 * N + col]) = make_float2(v00, v01);
                *reinterpret_cast<float2*>(&C[(size_t)r1 * N + col]) = make_float2(v10, v11);
            }
        }
    }
}

// ---------------- fp32 -> bf16 hi/lo splits --------------------------------
__device__ __forceinline__ void split4(const float* src, __nv_bfloat16* hi,
                                       __nv_bfloat16* lo, int i) {
    float4 v = *reinterpret_cast<const float4*>(src + i);
    __nv_bfloat16 h0 = __float2bfloat16(v.x), h1 = __float2bfloat16(v.y);
    __nv_bfloat16 h2 = __float2bfloat16(v.z), h3 = __float2bfloat16(v.w);
    __nv_bfloat16 l0 = __float2bfloat16(v.x - __bfloat162float(h0));
    __nv_bfloat16 l1 = __float2bfloat16(v.y - __bfloat162float(h1));
    __nv_bfloat16 l2 = __float2bfloat16(v.z - __bfloat162float(h2));
    __nv_bfloat16 l3 = __float2bfloat16(v.w - __bfloat162float(h3));
    *reinterpret_cast<uint2*>(&hi[i]) = make_uint2(pack_bf2(h0, h1), pack_bf2(h2, h3));
    *reinterpret_cast<uint2*>(&lo[i]) = make_uint2(pack_bf2(l0, l1), pack_bf2(l2, l3));
}

__global__ __launch_bounds__(256) void split_weights_kernel(
    const float* __restrict__ W1, __nv_bfloat16* __restrict__ w1h, __nv_bfloat16* __restrict__ w1l,
    const float* __restrict__ W2, __nv_bfloat16* __restrict__ w2h, __nv_bfloat16* __restrict__ w2l,
    const float* __restrict__ W3, __nv_bfloat16* __restrict__ w3h, __nv_bfloat16* __restrict__ w3l)
{
    const int N1 = H1_ * D_IN, N2 = H2_ * H1_, N3 = E_ * H2_;
    int i = (blockIdx.x * 256 + threadIdx.x) * 4;
    if (i < N1)               split4(W1, w1h, w1l, i);
    else if (i < N1 + N2)     split4(W2, w2h, w2l, i - N1);
    else if (i < N1 + N2 + N3) split4(W3, w3h, w3l, i - N1 - N2);
}

__global__ __launch_bounds__(256) void split_state_kernel(
    const float* __restrict__ src,
    __nv_bfloat16* __restrict__ hi, __nv_bfloat16* __restrict__ lo)
{
    int i = (blockIdx.x * 256 + threadIdx.x) * 4;
    split4(src, hi, lo, i);
}

// ============ fused shuffle: 5 x (attention + LSTM) in one kernel ==========
// One block per batch, 512 threads. qt/ct/attended live in SMEM.
__global__ __launch_bounds__(512) void shuffle_kernel(
    const float* __restrict__ emb, const int* __restrict__ length,
    const float* __restrict__ W_ih, const float* __restrict__ W_hh,
    const float* __restrict__ b_ih, const float* __restrict__ b_hh,
    float* __restrict__ out)
{
    const int b    = blockIdx.x;
    const int tid  = threadIdx.x;
    const int warp = tid >> 5, lane = tid & 31;

    __shared__ __align__(16) float s_q[H_];      // qt
    __shared__ __align__(16) float s_c[H_];      // ct
    __shared__ __align__(16) float s_x[E_];      // attended
    __shared__ __align__(16) float s_w[F_];      // logits / softmax weights
    __shared__ __align__(16) float s_g[4 * H_];  // lstm gates
    __shared__ __align__(16) float s_part[16][E_];
    __shared__ float s_red[512];

    if (tid < H_) { s_q[tid] = 0.f; s_c[tid] = 0.f; }
    __syncthreads();

    const int len = length[b];
    const float* eb = emb + (size_t)b * F_ * E_;
    const float4* q4 = reinterpret_cast<const float4*>(s_q);
    const float4* x4 = reinterpret_cast<const float4*>(s_x);

    for (int it = 0; it < NSH; it++) {
        // ---- logits: warp per row (float4 loads) ----
        for (int f = warp; f < F_; f += 16) {
            const float4* r4 = reinterpret_cast<const float4*>(eb + (size_t)f * E_);
            float d = 0.f;
#pragma unroll
            for (int j = 0; j < 2; j++) {
                float4 v = r4[lane + 32 * j];
                float4 q = q4[lane + 32 * j];
                d = fmaf(v.x, q.x, d); d = fmaf(v.y, q.y, d);
                d = fmaf(v.z, q.z, d); d = fmaf(v.w, q.w, d);
            }
#pragma unroll
            for (int o = 16; o; o >>= 1) d += __shfl_xor_sync(0xffffffffu, d, o);
            if (lane == 0) s_w[f] = (f < len) ? d : -1e30f;
        }
        __syncthreads();

        // ---- softmax max ----
        s_red[tid] = fmaxf(s_w[tid], s_w[tid + 512]);
        __syncthreads();
        for (int s = 256; s > 0; s >>= 1) {
            if (tid < s) s_red[tid] = fmaxf(s_red[tid], s_red[tid + s]);
            __syncthreads();
        }
        const float mx = s_red[0];
        __syncthreads();

        // ---- exp + sum (masked: exp underflows to exact 0) ----
        float e0 = expf(s_w[tid] - mx);
        float e1 = expf(s_w[tid + 512] - mx);
        s_w[tid] = e0; s_w[tid + 512] = e1;
        s_red[tid] = e0 + e1;
        __syncthreads();
        for (int s = 256; s > 0; s >>= 1) {
            if (tid < s) s_red[tid] += s_red[tid + s];
            __syncthreads();
        }
        const float inv = 1.f / s_red[0];
        __syncthreads();

        // ---- attended: warp w covers rows [w*64, w*64+64) ----
        float4 a0 = make_float4(0.f, 0.f, 0.f, 0.f);
        float4 a1 = make_float4(0.f, 0.f, 0.f, 0.f);
        const int fb = warp * 64;
#pragma unroll 4
        for (int ff = 0; ff < 64; ff++) {
            const int f = fb + ff;
            const float wf = s_w[f];
            const float4* r4 = reinterpret_cast<const float4*>(eb + (size_t)f * E_);
            float4 v0 = r4[lane], v1 = r4[lane + 32];
            a0.x = fmaf(wf, v0.x, a0.x); a0.y = fmaf(wf, v0.y, a0.y);
            a0.z = fmaf(wf, v0.z, a0.z); a0.w = fmaf(wf, v0.w, a0.w);
            a1.x = fmaf(wf, v1.x, a1.x); a1.y = fmaf(wf, v1.y, a1.y);
            a1.z = fmaf(wf, v1.z, a1.z); a1.w = fmaf(wf, v1.w, a1.w);
        }
        {
            float4* sp = reinterpret_cast<float4*>(s_part[warp]);
            sp[lane] = a0;
            sp[lane + 32] = a1;
        }
        __syncthreads();
        if (tid < E_) {
            float s = 0.f;
#pragma unroll
            for (int w = 0; w < 16; w++) s += s_part[w][tid];
            s_x[tid] = s * inv;
        }
        __syncthreads();

        // ---- LSTM gates: warp per 64 rows ----
        for (int j = warp * 64, je = j + 64; j < je; j++) {
            const float4* wi4 = reinterpret_cast<const float4*>(W_ih + (size_t)j * E_);
            const float4* wh4 = reinterpret_cast<const float4*>(W_hh + (size_t)j * H_);
            float d = 0.f;
#pragma unroll
            for (int jj = 0; jj < 2; jj++) {
                float4 wv = wi4[lane + 32 * jj], xv = x4[lane + 32 * jj];
                d = fmaf(wv.x, xv.x, d); d = fmaf(wv.y, xv.y, d);
                d = fmaf(wv.z, xv.z, d); d = fmaf(wv.w, xv.w, d);
                float4 hv = wh4[lane + 32 * jj], qv = q4[lane + 32 * jj];
                d = fmaf(hv.x, qv.x, d); d = fmaf(hv.y, qv.y, d);
                d = fmaf(hv.z, qv.z, d); d = fmaf(hv.w, qv.w, d);
            }
#pragma unroll
            for (int o = 16; o; o >>= 1) d += __shfl_xor_sync(0xffffffffu, d, o);
            if (lane == 0) s_g[j] = d + b_ih[j] + b_hh[j];
        }
        __syncthreads();

        // ---- state update (gate order i, f, g, o) ----
        if (tid < H_) {
            const float gi = 1.f / (1.f + expf(-s_g[tid]));
            const float gf = 1.f / (1.f + expf(-s_g[H_ + tid]));
            const float gg = tanhf(s_g[2 * H_ + tid]);
            const float go = 1.f / (1.f + expf(-s_g[3 * H_ + tid]));
            const float c = gf * s_c[tid] + gi * gg;
            s_c[tid] = c;
            s_q[tid] = go * tanhf(c);
        }
        __syncthreads();
    }

    // ---- output: concat(attended, qt) ----
    out[b * (E_ + H_) + tid] = (tid < E_) ? s_x[tid] : s_q[tid - E_];
}

// ---------------- launch ----------------------------------------------------
extern "C" void kernel_launch(void* const* d_in, const int* in_sizes, int n_in,
                              void* d_out, int out_size)
{
    const float* state = (const float*)d_in[0];
    const int*   length= (const int*)  d_in[1];
    const float* W1    = (const float*)d_in[2];
    const float* b1    = (const float*)d_in[3];
    const float* W2    = (const float*)d_in[4];
    const float* b2    = (const float*)d_in[5];
    const float* W3    = (const float*)d_in[6];
    const float* b3    = (const float*)d_in[7];
    const float* W_ih  = (const float*)d_in[8];
    const float* W_hh  = (const float*)d_in[9];
    const float* b_ih  = (const float*)d_in[10];
    const float* b_hh  = (const float*)d_in[11];
    float* out = (float*)d_out;

    __nv_bfloat16 *sth, *stl, *h1h, *h1l, *h2h, *h2l;
    __nv_bfloat16 *w1h, *w1l, *w2h, *w2l, *w3h, *w3l;
    float *emb;
    cudaGetSymbolAddress((void**)&sth, g_sth);
    cudaGetSymbolAddress((void**)&stl, g_stl);
    cudaGetSymbolAddress((void**)&h1h, g_h1h);
    cudaGetSymbolAddress((void**)&h1l, g_h1l);
    cudaGetSymbolAddress((void**)&h2h, g_h2h);
    cudaGetSymbolAddress((void**)&h2l, g_h2l);
    cudaGetSymbolAddress((void**)&w1h, g_w1h);
    cudaGetSymbolAddress((void**)&w1l, g_w1l);
    cudaGetSymbolAddress((void**)&w2h, g_w2h);
    cudaGetSymbolAddress((void**)&w2l, g_w2l);
    cudaGetSymbolAddress((void**)&w3h, g_w3h);
    cudaGetSymbolAddress((void**)&w3l, g_w3l);
    cudaGetSymbolAddress((void**)&emb, g_emb);

    cudaFuncSetAttribute(gemm_mma_kernel<1, 1>,
                         cudaFuncAttributeMaxDynamicSharedMemorySize, GEMM_SM);
    cudaFuncSetAttribute(gemm_mma_kernel<0, 0>,
                         cudaFuncAttributeMaxDynamicSharedMemorySize, GEMM_SM);

    // 1: weight splits (one launch)
    {
        int n = H1_ * D_IN + H2_ * H1_ + E_ * H2_;   // 458752
        split_weights_kernel<<<n / 1024, 256>>>(W1, w1h, w1l, W2, w2h, w2l, W3, w3h, w3l);
    }
    // 2: state split
    split_state_kernel<<<(MROWS * D_IN) / 1024, 256>>>(state, sth, stl);

    // 3-5: embedder MLP on HMMA tensor cores
    {
        dim3 g1(H1_ / 128, MROWS / 128);
        gemm_mma_kernel<1, 1><<<g1, 256, GEMM_SM>>>(
            MROWS, H1_, D_IN, sth, stl, w1h, w1l, b1, nullptr, h1h, h1l);
        dim3 g2(H2_ / 128, MROWS / 128);
        gemm_mma_kernel<1, 1><<<g2, 256, GEMM_SM>>>(
            MROWS, H2_, H1_, h1h, h1l, w2h, w2l, b2, nullptr, h2h, h2l);
        dim3 g3(E_ / 128, MROWS / 128);
        gemm_mma_kernel<0, 0><<<g3, 256, GEMM_SM>>>(
            MROWS, E_, H2_, h2h, h2l, w3h, w3l, b3, emb, nullptr, nullptr);
    }

    // 6: fused shuffle loop (attention + LSTM x5) + output
    shuffle_kernel<<<B_, 512>>>(emb, length, W_ih, W_hh, b_ih, b_hh, out);
}

// round 5
// speedup vs baseline: 3.8292x; 1.2126x over previous
#include <cuda_runtime.h>
#include <cuda_bf16.h>
#include <math.h>
#include <stdint.h>

// Problem constants
#define B_    128
#define F_    1024
#define D_IN  128
#define H1_   512
#define H2_   512
#define E_    256
#define H_    256
#define NSH   5
#define MROWS (B_ * F_)   // 131072

// ---------------- scratch (device globals; no allocation allowed) ----------
__device__ __nv_bfloat16 g_sth[(size_t)MROWS * D_IN];
__device__ __nv_bfloat16 g_stl[(size_t)MROWS * D_IN];
__device__ __nv_bfloat16 g_h1h[(size_t)MROWS * H1_];
__device__ __nv_bfloat16 g_h1l[(size_t)MROWS * H1_];
__device__ __nv_bfloat16 g_h2h[(size_t)MROWS * H2_];
__device__ __nv_bfloat16 g_h2l[(size_t)MROWS * H2_];
__device__ __nv_bfloat16 g_w1h[H1_ * D_IN], g_w1l[H1_ * D_IN];
__device__ __nv_bfloat16 g_w2h[H2_ * H1_],  g_w2l[H2_ * H1_];
__device__ __nv_bfloat16 g_w3h[E_ * H2_],   g_w3l[E_ * H2_];
__device__ float g_emb[(size_t)MROWS * E_];   // 134 MB

// ===================== low-level helpers ===================================
__device__ __forceinline__ uint32_t smem_u32(const void* p) {
    uint32_t a;
    asm("{ .reg .u64 t; cvta.to.shared.u64 t, %1; cvt.u32.u64 %0, t; }"
        : "=r"(a) : "l"(p));
    return a;
}

__device__ __forceinline__ void cp_async16(uint32_t dst, const void* src) {
    asm volatile("cp.async.cg.shared.global [%0], [%1], 16;\n"
                 :: "r"(dst), "l"(src));
}
#define CP_COMMIT() asm volatile("cp.async.commit_group;\n" ::: "memory")
#define CP_WAIT1()  asm volatile("cp.async.wait_group 1;\n" ::: "memory")
#define CP_WAIT0()  asm volatile("cp.async.wait_group 0;\n" ::: "memory")

__device__ __forceinline__ void ldsm4(uint32_t* r, uint32_t addr) {
    asm volatile("ldmatrix.sync.aligned.m8n8.x4.shared.b16 {%0,%1,%2,%3}, [%4];\n"
                 : "=r"(r[0]), "=r"(r[1]), "=r"(r[2]), "=r"(r[3]) : "r"(addr));
}

__device__ __forceinline__ void mma16816(float* d, const uint32_t* a, const uint32_t* b) {
    asm volatile(
        "mma.sync.aligned.m16n8k16.row.col.f32.bf16.bf16.f32 "
        "{%0,%1,%2,%3}, {%4,%5,%6,%7}, {%8,%9}, {%0,%1,%2,%3};\n"
        : "+f"(d[0]), "+f"(d[1]), "+f"(d[2]), "+f"(d[3])
        : "r"(a[0]), "r"(a[1]), "r"(a[2]), "r"(a[3]), "r"(b[0]), "r"(b[1]));
}

__device__ __forceinline__ uint32_t pack_bf2(__nv_bfloat16 a, __nv_bfloat16 b) {
    __nv_bfloat162 t = __halves2bfloat162(a, b);
    return reinterpret_cast<uint32_t&>(t);
}

// =================== HMMA GEMM: C = act(A @ W^T + bias) =====================
// A as bf16 hi/lo [M,K]; W as bf16 hi/lo [N,K]. D = Ah*Wh + Al*Wh + Ah*Wl.
// CTA tile 128x128, 8 warps (2x4), warp tile 64x32, BK=32, 2-stage cp.async,
// 2 CTAs/SM. SMEM rows padded to 80B -> conflict-free ldmatrix.
static constexpr int TILE_B   = 128 * 80;          // 10240 B per operand tile
static constexpr int STAGE_B  = 4 * TILE_B;        // Ah|Al|Wh|Wl = 40960 B
static constexpr int GEMM_SM  = 2 * STAGE_B;       // 81920 B

template <int ACT, int OUT_BF>
__global__ __launch_bounds__(256, 2) void gemm_mma_kernel(
    int M, int N, int K,
    const __nv_bfloat16* __restrict__ Ah, const __nv_bfloat16* __restrict__ Al,
    const __nv_bfloat16* __restrict__ Wh, const __nv_bfloat16* __restrict__ Wl,
    const float* __restrict__ bias,
    float* __restrict__ C,
    __nv_bfloat16* __restrict__ Ch, __nv_bfloat16* __restrict__ Cl)
{
    extern __shared__ char smem[];
    const uint32_t sbase = smem_u32(smem);
    const int tid  = threadIdx.x;
    const int lane = tid & 31;
    const int wid  = tid >> 5;
    const int m0 = blockIdx.y * 128;
    const int n0 = blockIdx.x * 128;
    const int wm = (wid & 1) * 64;     // warp m-offset
    const int wn = (wid >> 1) * 32;    // warp n-offset

    float acc[4][4][4];
#pragma unroll
    for (int i = 0; i < 4; i++)
#pragma unroll
        for (int j = 0; j < 4; j++)
#pragma unroll
            for (int k = 0; k < 4; k++) acc[i][j][k] = 0.f;

    // per-thread cp.async geometry
    const int prow = tid >> 2;
    const int pch  = (tid & 3) * 8;
    const uint32_t sd_base = sbase + prow * 80 + pch * 2;

    // ldmatrix per-lane offsets (relative to stage base)
    uint32_t aoff[4], boff[2];
#pragma unroll
    for (int am = 0; am < 4; am++)
        aoff[am] = (uint32_t)((wm + am * 16 + (lane & 15)) * 80 + (lane >> 4) * 16);
#pragma unroll
    for (int pb = 0; pb < 2; pb++)
        boff[pb] = (uint32_t)((wn + pb * 16 + (lane & 7) + ((lane >> 1) & 8)) * 80
                              + ((lane >> 3) & 1) * 16);

    const int NC = K >> 5;   // chunks of 32

    auto prefetch = [&](int cc, int st) {
        const uint32_t so = sd_base + st * STAGE_B;
        const int kk = cc * 32 + pch;
#pragma unroll
        for (int i = 0; i < 8; i++) {
            const __nv_bfloat16* bp = (i < 2) ? Ah : (i < 4) ? Al : (i < 6) ? Wh : Wl;
            const int rb = ((i < 4) ? m0 : n0) + (i & 1) * 64 + prow;
            cp_async16(so + (i >> 1) * TILE_B + (i & 1) * 64 * 80,
                       bp + (size_t)rb * K + kk);
        }
        CP_COMMIT();
    };

    prefetch(0, 0);

    for (int cc = 0; cc < NC; cc++) {
        if (cc + 1 < NC) { prefetch(cc + 1, (cc + 1) & 1); CP_WAIT1(); }
        else             { CP_WAIT0(); }
        __syncthreads();

        const uint32_t st = sbase + (cc & 1) * STAGE_B;
#pragma unroll
        for (int s = 0; s < 2; s++) {
            uint32_t ah[4][4];
#pragma unroll
            for (int am = 0; am < 4; am++) ldsm4(ah[am], st + aoff[am] + s * 32);
            uint32_t b0[4][2];
#pragma unroll
            for (int pb = 0; pb < 2; pb++) {
                uint32_t r[4];
                ldsm4(r, st + 2 * TILE_B + boff[pb] + s * 32);
                b0[2 * pb][0] = r[0]; b0[2 * pb][1] = r[1];
                b0[2 * pb + 1][0] = r[2]; b0[2 * pb + 1][1] = r[3];
            }
#pragma unroll
            for (int am = 0; am < 4; am++)
#pragma unroll
                for (int an = 0; an < 4; an++) mma16816(acc[am][an], ah[am], b0[an]);

            {
                uint32_t al[4][4];
#pragma unroll
                for (int am = 0; am < 4; am++) ldsm4(al[am], st + TILE_B + aoff[am] + s * 32);
#pragma unroll
                for (int am = 0; am < 4; am++)
#pragma unroll
                    for (int an = 0; an < 4; an++) mma16816(acc[am][an], al[am], b0[an]);
            }
            {
                uint32_t b1[4][2];
#pragma unroll
                for (int pb = 0; pb < 2; pb++) {
                    uint32_t r[4];
                    ldsm4(r, st + 3 * TILE_B + boff[pb] + s * 32);
                    b1[2 * pb][0] = r[0]; b1[2 * pb][1] = r[1];
                    b1[2 * pb + 1][0] = r[2]; b1[2 * pb + 1][1] = r[3];
                }
#pragma unroll
                for (int am = 0; am < 4; am++)
#pragma unroll
                    for (int an = 0; an < 4; an++) mma16816(acc[am][an], ah[am], b1[an]);
            }
        }
        __syncthreads();
    }

    // epilogue: bias (+ReLU), store fp32 or bf16 hi/lo
#pragma unroll
    for (int am = 0; am < 4; am++) {
        const int r0 = m0 + wm + am * 16 + (lane >> 2);
        const int r1 = r0 + 8;
#pragma unroll
        for (int an = 0; an < 4; an++) {
            const int col = n0 + wn + an * 8 + ((lane & 3) << 1);
            const float bz0 = __ldg(&bias[col]);
            const float bz1 = __ldg(&bias[col + 1]);
            float v00 = acc[am][an][0] + bz0;
            float v01 = acc[am][an][1] + bz1;
            float v10 = acc[am][an][2] + bz0;
            float v11 = acc[am][an][3] + bz1;
            if (ACT) {
                v00 = fmaxf(v00, 0.f); v01 = fmaxf(v01, 0.f);
                v10 = fmaxf(v10, 0.f); v11 = fmaxf(v11, 0.f);
            }
            if (OUT_BF) {
                __nv_bfloat16 h00 = __float2bfloat16(v00), h01 = __float2bfloat16(v01);
                __nv_bfloat16 h10 = __float2bfloat16(v10), h11 = __float2bfloat16(v11);
                __nv_bfloat16 l00 = __float2bfloat16(v00 - __bfloat162float(h00));
                __nv_bfloat16 l01 = __float2bfloat16(v01 - __bfloat162float(h01));
                __nv_bfloat16 l10 = __float2bfloat16(v10 - __bfloat162float(h10));
                __nv_bfloat16 l11 = __float2bfloat16(v11 - __bfloat162float(h11));
                *reinterpret_cast<uint32_t*>(&Ch[(size_t)r0 * N + col]) = pack_bf2(h00, h01);
                *reinterpret_cast<uint32_t*>(&Cl[(size_t)r0 * N + col]) = pack_bf2(l00, l01);
                *reinterpret_cast<uint32_t*>(&Ch[(size_t)r1 * N + col]) = pack_bf2(h10, h11);
                *reinterpret_cast<uint32_t*>(&Cl[(size_t)r1 * N + col]) = pack_bf2(l10, l11);
            } else {
                *reinterpret_cast<float2*>(&C[(size_t)r0 * N + col]) = make_float2(v00, v01);
                *reinterpret_cast<float2*>(&C[(size_t)r1 * N + col]) = make_float2(v10, v11);
            }
        }
    }
}

// ---------------- fp32 -> bf16 hi/lo splits --------------------------------
__device__ __forceinline__ void split4(const float* src, __nv_bfloat16* hi,
                                       __nv_bfloat16* lo, int i) {
    float4 v = *reinterpret_cast<const float4*>(src + i);
    __nv_bfloat16 h0 = __float2bfloat16(v.x), h1 = __float2bfloat16(v.y);
    __nv_bfloat16 h2 = __float2bfloat16(v.z), h3 = __float2bfloat16(v.w);
    __nv_bfloat16 l0 = __float2bfloat16(v.x - __bfloat162float(h0));
    __nv_bfloat16 l1 = __float2bfloat16(v.y - __bfloat162float(h1));
    __nv_bfloat16 l2 = __float2bfloat16(v.z - __bfloat162float(h2));
    __nv_bfloat16 l3 = __float2bfloat16(v.w - __bfloat162float(h3));
    *reinterpret_cast<uint2*>(&hi[i]) = make_uint2(pack_bf2(h0, h1), pack_bf2(h2, h3));
    *reinterpret_cast<uint2*>(&lo[i]) = make_uint2(pack_bf2(l0, l1), pack_bf2(l2, l3));
}

__global__ __launch_bounds__(256) void split_weights_kernel(
    const float* __restrict__ W1, __nv_bfloat16* __restrict__ w1h, __nv_bfloat16* __restrict__ w1l,
    const float* __restrict__ W2, __nv_bfloat16* __restrict__ w2h, __nv_bfloat16* __restrict__ w2l,
    const float* __restrict__ W3, __nv_bfloat16* __restrict__ w3h, __nv_bfloat16* __restrict__ w3l)
{
    const int N1 = H1_ * D_IN, N2 = H2_ * H1_, N3 = E_ * H2_;
    int i = (blockIdx.x * 256 + threadIdx.x) * 4;
    if (i < N1)                split4(W1, w1h, w1l, i);
    else if (i < N1 + N2)      split4(W2, w2h, w2l, i - N1);
    else if (i < N1 + N2 + N3) split4(W3, w3h, w3l, i - N1 - N2);
}

__global__ __launch_bounds__(256) void split_state_kernel(
    const float* __restrict__ src,
    __nv_bfloat16* __restrict__ hi, __nv_bfloat16* __restrict__ lo)
{
    int i = (blockIdx.x * 256 + threadIdx.x) * 4;
    split4(src, hi, lo, i);
}

// ============ fused shuffle: 5 x (online-softmax attention + LSTM) =========
// One block per batch, 1024 threads (32 warps). Single emb pass per iteration:
// warp w streams f-rows [w*32, w*32+32), maintaining flash-style (m, l, acc).
__global__ __launch_bounds__(1024) void shuffle_kernel(
    const float* __restrict__ emb, const int* __restrict__ length,
    const float* __restrict__ W_ih, const float* __restrict__ W_hh,
    const float* __restrict__ b_ih, const float* __restrict__ b_hh,
    float* __restrict__ out)
{
    const int b    = blockIdx.x;
    const int tid  = threadIdx.x;
    const int warp = tid >> 5, lane = tid & 31;

    __shared__ __align__(16) float s_q[H_];         // qt
    __shared__ __align__(16) float s_c[H_];         // ct
    __shared__ __align__(16) float s_x[E_];         // attended
    __shared__ __align__(16) float s_g[4 * H_];     // lstm gates
    __shared__ __align__(16) float s_part[32][E_ + 4];
    __shared__ float s_m[32], s_l[32], s_fac[32];
    __shared__ float s_invL;

    if (tid < H_) { s_q[tid] = 0.f; s_c[tid] = 0.f; }
    __syncthreads();

    const int len = length[b];
    const float* eb = emb + (size_t)b * F_ * E_;
    const float4* q4 = reinterpret_cast<const float4*>(s_q);
    const float4* x4 = reinterpret_cast<const float4*>(s_x);

    for (int it = 0; it < NSH; it++) {
        // ---- single-pass attention: logits + online softmax + attended ----
        float m = -INFINITY, l = 0.f;
        float4 a0 = make_float4(0.f, 0.f, 0.f, 0.f);
        float4 a1 = make_float4(0.f, 0.f, 0.f, 0.f);
        const float4 qv0 = q4[lane], qv1 = q4[lane + 32];
        const int fb = warp * 32;
#pragma unroll 2
        for (int ff = 0; ff < 32; ff++) {
            const int f = fb + ff;
            const float4* r4 = reinterpret_cast<const float4*>(eb + (size_t)f * E_);
            const float4 v0 = r4[lane], v1 = r4[lane + 32];
            float d = v0.x * qv0.x + v0.y * qv0.y + v0.z * qv0.z + v0.w * qv0.w;
            d = fmaf(v1.x, qv1.x, d); d = fmaf(v1.y, qv1.y, d);
            d = fmaf(v1.z, qv1.z, d); d = fmaf(v1.w, qv1.w, d);
#pragma unroll
            for (int o = 16; o; o >>= 1) d += __shfl_xor_sync(0xffffffffu, d, o);
            if (f < len) {
                const float mn = fmaxf(m, d);
                const float sc = expf(m - mn);    // 0 on first valid row
                const float p  = expf(d - mn);
                l = l * sc + p;
                a0.x = fmaf(a0.x, sc, p * v0.x); a0.y = fmaf(a0.y, sc, p * v0.y);
                a0.z = fmaf(a0.z, sc, p * v0.z); a0.w = fmaf(a0.w, sc, p * v0.w);
                a1.x = fmaf(a1.x, sc, p * v1.x); a1.y = fmaf(a1.y, sc, p * v1.y);
                a1.z = fmaf(a1.z, sc, p * v1.z); a1.w = fmaf(a1.w, sc, p * v1.w);
                m = mn;
            }
        }
        {
            float4* sp = reinterpret_cast<float4*>(s_part[warp]);
            sp[lane] = a0;
            sp[lane + 32] = a1;
            if (lane == 0) { s_m[warp] = m; s_l[warp] = l; }
        }
        __syncthreads();

        // ---- combine 32 warp-partials (warp 0) ----
        if (tid < 32) {
            const float mw = s_m[tid];
            float M = mw;
#pragma unroll
            for (int o = 16; o; o >>= 1) M = fmaxf(M, __shfl_xor_sync(0xffffffffu, M, o));
            const float fac = expf(mw - M);       // 0 if warp saw no valid rows
            s_fac[tid] = fac;
            float L = s_l[tid] * fac;
#pragma unroll
            for (int o = 16; o; o >>= 1) L += __shfl_xor_sync(0xffffffffu, L, o);
            if (tid == 0) s_invL = 1.f / L;
        }
        __syncthreads();

        if (tid < E_) {
            float s = 0.f;
#pragma unroll
            for (int w = 0; w < 32; w++) s = fmaf(s_part[w][tid], s_fac[w], s);
            s_x[tid] = s * s_invL;
        }
        __syncthreads();

        // ---- LSTM gates: warp per 32 rows ----
        {
            const float4 xv0 = x4[lane], xv1 = x4[lane + 32];
            const float4 qv0b = q4[lane], qv1b = q4[lane + 32];
            for (int j = warp * 32, je = j + 32; j < je; j++) {
                const float4* wi4 = reinterpret_cast<const float4*>(W_ih + (size_t)j * E_);
                const float4* wh4 = reinterpret_cast<const float4*>(W_hh + (size_t)j * H_);
                const float4 w0 = wi4[lane], w1 = wi4[lane + 32];
                const float4 h0 = wh4[lane], h1 = wh4[lane + 32];
                float d = w0.x * xv0.x + w0.y * xv0.y + w0.z * xv0.z + w0.w * xv0.w;
                d = fmaf(w1.x, xv1.x, d); d = fmaf(w1.y, xv1.y, d);
                d = fmaf(w1.z, xv1.z, d); d = fmaf(w1.w, xv1.w, d);
                d = fmaf(h0.x, qv0b.x, d); d = fmaf(h0.y, qv0b.y, d);
                d = fmaf(h0.z, qv0b.z, d); d = fmaf(h0.w, qv0b.w, d);
                d = fmaf(h1.x, qv1b.x, d); d = fmaf(h1.y, qv1b.y, d);
                d = fmaf(h1.z, qv1b.z, d); d = fmaf(h1.w, qv1b.w, d);
#pragma unroll
                for (int o = 16; o; o >>= 1) d += __shfl_xor_sync(0xffffffffu, d, o);
                if (lane == 0) s_g[j] = d + b_ih[j] + b_hh[j];
            }
        }
        __syncthreads();

        // ---- state update (gate order i, f, g, o) ----
        if (tid < H_) {
            const float gi = 1.f / (1.f + expf(-s_g[tid]));
            const float gf = 1.f / (1.f + expf(-s_g[H_ + tid]));
            const float gg = tanhf(s_g[2 * H_ + tid]);
            const float go = 1.f / (1.f + expf(-s_g[3 * H_ + tid]));
            const float c = gf * s_c[tid] + gi * gg;
            s_c[tid] = c;
            s_q[tid] = go * tanhf(c);
        }
        __syncthreads();
    }

    // ---- output: concat(attended, qt) ----
    if (tid < E_ + H_)
        out[b * (E_ + H_) + tid] = (tid < E_) ? s_x[tid] : s_q[tid - E_];
}

// ---------------- launch ----------------------------------------------------
extern "C" void kernel_launch(void* const* d_in, const int* in_sizes, int n_in,
                              void* d_out, int out_size)
{
    const float* state = (const float*)d_in[0];
    const int*   length= (const int*)  d_in[1];
    const float* W1    = (const float*)d_in[2];
    const float* b1    = (const float*)d_in[3];
    const float* W2    = (const float*)d_in[4];
    const float* b2    = (const float*)d_in[5];
    const float* W3    = (const float*)d_in[6];
    const float* b3    = (const float*)d_in[7];
    const float* W_ih  = (const float*)d_in[8];
    const float* W_hh  = (const float*)d_in[9];
    const float* b_ih  = (const float*)d_in[10];
    const float* b_hh  = (const float*)d_in[11];
    float* out = (float*)d_out;

    __nv_bfloat16 *sth, *stl, *h1h, *h1l, *h2h, *h2l;
    __nv_bfloat16 *w1h, *w1l, *w2h, *w2l, *w3h, *w3l;
    float *emb;
    cudaGetSymbolAddress((void**)&sth, g_sth);
    cudaGetSymbolAddress((void**)&stl, g_stl);
    cudaGetSymbolAddress((void**)&h1h, g_h1h);
    cudaGetSymbolAddress((void**)&h1l, g_h1l);
    cudaGetSymbolAddress((void**)&h2h, g_h2h);
    cudaGetSymbolAddress((void**)&h2l, g_h2l);
    cudaGetSymbolAddress((void**)&w1h, g_w1h);
    cudaGetSymbolAddress((void**)&w1l, g_w1l);
    cudaGetSymbolAddress((void**)&w2h, g_w2h);
    cudaGetSymbolAddress((void**)&w2l, g_w2l);
    cudaGetSymbolAddress((void**)&w3h, g_w3h);
    cudaGetSymbolAddress((void**)&w3l, g_w3l);
    cudaGetSymbolAddress((void**)&emb, g_emb);

    cudaFuncSetAttribute(gemm_mma_kernel<1, 1>,
                         cudaFuncAttributeMaxDynamicSharedMemorySize, GEMM_SM);
    cudaFuncSetAttribute(gemm_mma_kernel<0, 0>,
                         cudaFuncAttributeMaxDynamicSharedMemorySize, GEMM_SM);

    // 1: weight splits
    {
        int n = H1_ * D_IN + H2_ * H1_ + E_ * H2_;
        split_weights_kernel<<<n / 1024, 256>>>(W1, w1h, w1l, W2, w2h, w2l, W3, w3h, w3l);
    }
    // 2: state split
    split_state_kernel<<<(MROWS * D_IN) / 1024, 256>>>(state, sth, stl);

    // 3-5: embedder MLP on HMMA tensor cores
    {
        dim3 g1(H1_ / 128, MROWS / 128);
        gemm_mma_kernel<1, 1><<<g1, 256, GEMM_SM>>>(
            MROWS, H1_, D_IN, sth, stl, w1h, w1l, b1, nullptr, h1h, h1l);
        dim3 g2(H2_ / 128, MROWS / 128);
        gemm_mma_kernel<1, 1><<<g2, 256, GEMM_SM>>>(
            MROWS, H2_, H1_, h1h, h1l, w2h, w2l, b2, nullptr, h2h, h2l);
        dim3 g3(E_ / 128, MROWS / 128);
        gemm_mma_kernel<0, 0><<<g3, 256, GEMM_SM>>>(
            MROWS, E_, H2_, h2h, h2l, w3h, w3l, b3, emb, nullptr, nullptr);
    }

    // 6: fused shuffle loop (online-softmax attention + LSTM x5) + output
    shuffle_kernel<<<B_, 1024>>>(emb, length, W_ih, W_hh, b_ih, b_hh, out);
}

// round 6
// speedup vs baseline: 3.8372x; 1.0021x over previous
#include <cuda_runtime.h>
#include <cuda_bf16.h>
#include <math.h>
#include <stdint.h>

// Problem constants
#define B_    128
#define F_    1024
#define D_IN  128
#define H1_   512
#define H2_   512
#define E_    256
#define H_    256
#define NSH   5
#define MROWS (B_ * F_)   // 131072

// ---------------- scratch (device globals; no allocation allowed) ----------
__device__ __nv_bfloat16 g_sth[(size_t)MROWS * D_IN];
__device__ __nv_bfloat16 g_stl[(size_t)MROWS * D_IN];
__device__ __nv_bfloat16 g_h1h[(size_t)MROWS * H1_];
__device__ __nv_bfloat16 g_h1l[(size_t)MROWS * H1_];
__device__ __nv_bfloat16 g_h2h[(size_t)MROWS * H2_];
__device__ __nv_bfloat16 g_h2l[(size_t)MROWS * H2_];
__device__ __nv_bfloat16 g_w1h[H1_ * D_IN], g_w1l[H1_ * D_IN];
__device__ __nv_bfloat16 g_w2h[H2_ * H1_],  g_w2l[H2_ * H1_];
__device__ __nv_bfloat16 g_w3h[E_ * H2_],   g_w3l[E_ * H2_];
__device__ float g_emb[(size_t)MROWS * E_];   // 134 MB

// ===================== low-level helpers ===================================
__device__ __forceinline__ uint32_t smem_u32(const void* p) {
    uint32_t a;
    asm("{ .reg .u64 t; cvta.to.shared.u64 t, %1; cvt.u32.u64 %0, t; }"
        : "=r"(a) : "l"(p));
    return a;
}

__device__ __forceinline__ void cp_async16(uint32_t dst, const void* src) {
    asm volatile("cp.async.cg.shared.global [%0], [%1], 16;\n"
                 :: "r"(dst), "l"(src));
}
#define CP_COMMIT() asm volatile("cp.async.commit_group;\n" ::: "memory")
#define CP_WAIT1()  asm volatile("cp.async.wait_group 1;\n" ::: "memory")
#define CP_WAIT0()  asm volatile("cp.async.wait_group 0;\n" ::: "memory")

__device__ __forceinline__ void ldsm4(uint32_t* r, uint32_t addr) {
    asm volatile("ldmatrix.sync.aligned.m8n8.x4.shared.b16 {%0,%1,%2,%3}, [%4];\n"
                 : "=r"(r[0]), "=r"(r[1]), "=r"(r[2]), "=r"(r[3]) : "r"(addr));
}

__device__ __forceinline__ void mma16816(float* d, const uint32_t* a, const uint32_t* b) {
    asm volatile(
        "mma.sync.aligned.m16n8k16.row.col.f32.bf16.bf16.f32 "
        "{%0,%1,%2,%3}, {%4,%5,%6,%7}, {%8,%9}, {%0,%1,%2,%3};\n"
        : "+f"(d[0]), "+f"(d[1]), "+f"(d[2]), "+f"(d[3])
        : "r"(a[0]), "r"(a[1]), "r"(a[2]), "r"(a[3]), "r"(b[0]), "r"(b[1]));
}

__device__ __forceinline__ uint32_t pack_bf2(__nv_bfloat16 a, __nv_bfloat16 b) {
    __nv_bfloat162 t = __halves2bfloat162(a, b);
    return reinterpret_cast<uint32_t&>(t);
}

// =================== HMMA GEMM: C = act(A @ W^T + bias) =====================
// A as bf16 hi/lo [M,K]; W as bf16 hi/lo [N,K]. D = Ah*Wh + Ah*Wl + Al*Wh.
// CTA tile 128x128, 8 warps (2x4), warp tile 64x32, BK=32, 2-stage cp.async,
// 2 CTAs/SM. SMEM rows padded to 80B -> conflict-free ldmatrix.
// Mainloop: 2 load points per subchunk (ah+b0+b1 up front, al mid-stream),
// 32 back-to-back MMAs before the next dependent LDSM.
static constexpr int TILE_B   = 128 * 80;          // 10240 B per operand tile
static constexpr int STAGE_B  = 4 * TILE_B;        // Ah|Al|Wh|Wl = 40960 B
static constexpr int GEMM_SM  = 2 * STAGE_B;       // 81920 B

template <int ACT, int OUT_BF>
__global__ __launch_bounds__(256, 2) void gemm_mma_kernel(
    int M, int N, int K,
    const __nv_bfloat16* __restrict__ Ah, const __nv_bfloat16* __restrict__ Al,
    const __nv_bfloat16* __restrict__ Wh, const __nv_bfloat16* __restrict__ Wl,
    const float* __restrict__ bias,
    float* __restrict__ C,
    __nv_bfloat16* __restrict__ Ch, __nv_bfloat16* __restrict__ Cl)
{
    extern __shared__ char smem[];
    const uint32_t sbase = smem_u32(smem);
    const int tid  = threadIdx.x;
    const int lane = tid & 31;
    const int wid  = tid >> 5;
    const int m0 = blockIdx.y * 128;
    const int n0 = blockIdx.x * 128;
    const int wm = (wid & 1) * 64;     // warp m-offset
    const int wn = (wid >> 1) * 32;    // warp n-offset

    float acc[4][4][4];
#pragma unroll
    for (int i = 0; i < 4; i++)
#pragma unroll
        for (int j = 0; j < 4; j++)
#pragma unroll
            for (int k = 0; k < 4; k++) acc[i][j][k] = 0.f;

    // per-thread cp.async geometry
    const int prow = tid >> 2;
    const int pch  = (tid & 3) * 8;
    const uint32_t sd_base = sbase + prow * 80 + pch * 2;

    // ldmatrix per-lane offsets (relative to stage base)
    uint32_t aoff[4], boff[2];
#pragma unroll
    for (int am = 0; am < 4; am++)
        aoff[am] = (uint32_t)((wm + am * 16 + (lane & 15)) * 80 + (lane >> 4) * 16);
#pragma unroll
    for (int pb = 0; pb < 2; pb++)
        boff[pb] = (uint32_t)((wn + pb * 16 + (lane & 7) + ((lane >> 1) & 8)) * 80
                              + ((lane >> 3) & 1) * 16);

    const int NC = K >> 5;   // chunks of 32

    auto prefetch = [&](int cc, int st) {
        const uint32_t so = sd_base + st * STAGE_B;
        const int kk = cc * 32 + pch;
#pragma unroll
        for (int i = 0; i < 8; i++) {
            const __nv_bfloat16* bp = (i < 2) ? Ah : (i < 4) ? Al : (i < 6) ? Wh : Wl;
            const int rb = ((i < 4) ? m0 : n0) + (i & 1) * 64 + prow;
            cp_async16(so + (i >> 1) * TILE_B + (i & 1) * 64 * 80,
                       bp + (size_t)rb * K + kk);
        }
        CP_COMMIT();
    };

    prefetch(0, 0);

    for (int cc = 0; cc < NC; cc++) {
        if (cc + 1 < NC) { prefetch(cc + 1, (cc + 1) & 1); CP_WAIT1(); }
        else             { CP_WAIT0(); }
        __syncthreads();

        const uint32_t st = sbase + (cc & 1) * STAGE_B;
#pragma unroll
        for (int s = 0; s < 2; s++) {
            // load ah (Ah), b0 (Wh), b1 (Wl) up front
            uint32_t ah[4][4];
#pragma unroll
            for (int am = 0; am < 4; am++) ldsm4(ah[am], st + aoff[am] + s * 32);
            uint32_t b0[4][2], b1[4][2];
#pragma unroll
            for (int pb = 0; pb < 2; pb++) {
                uint32_t r[4];
                ldsm4(r, st + 2 * TILE_B + boff[pb] + s * 32);
                b0[2 * pb][0] = r[0]; b0[2 * pb][1] = r[1];
                b0[2 * pb + 1][0] = r[2]; b0[2 * pb + 1][1] = r[3];
            }
#pragma unroll
            for (int pb = 0; pb < 2; pb++) {
                uint32_t r[4];
                ldsm4(r, st + 3 * TILE_B + boff[pb] + s * 32);
                b1[2 * pb][0] = r[0]; b1[2 * pb][1] = r[1];
                b1[2 * pb + 1][0] = r[2]; b1[2 * pb + 1][1] = r[3];
            }

            // group 1: ah * b0  (16 MMAs)
#pragma unroll
            for (int am = 0; am < 4; am++)
#pragma unroll
                for (int an = 0; an < 4; an++) mma16816(acc[am][an], ah[am], b0[an]);

            // issue al loads here so they complete under group 2's MMAs
            uint32_t al[4][4];
#pragma unroll
            for (int am = 0; am < 4; am++) ldsm4(al[am], st + TILE_B + aoff[am] + s * 32);

            // group 2: ah * b1  (16 MMAs, independent of al)
#pragma unroll
            for (int am = 0; am < 4; am++)
#pragma unroll
                for (int an = 0; an < 4; an++) mma16816(acc[am][an], ah[am], b1[an]);

            // group 3: al * b0  (16 MMAs)
#pragma unroll
            for (int am = 0; am < 4; am++)
#pragma unroll
                for (int an = 0; an < 4; an++) mma16816(acc[am][an], al[am], b0[an]);
        }
        __syncthreads();
    }

    // epilogue: bias (+ReLU), store fp32 or bf16 hi/lo
#pragma unroll
    for (int am = 0; am < 4; am++) {
        const int r0 = m0 + wm + am * 16 + (lane >> 2);
        const int r1 = r0 + 8;
#pragma unroll
        for (int an = 0; an < 4; an++) {
            const int col = n0 + wn + an * 8 + ((lane & 3) << 1);
            const float bz0 = __ldg(&bias[col]);
            const float bz1 = __ldg(&bias[col + 1]);
            float v00 = acc[am][an][0] + bz0;
            float v01 = acc[am][an][1] + bz1;
            float v10 = acc[am][an][2] + bz0;
            float v11 = acc[am][an][3] + bz1;
            if (ACT) {
                v00 = fmaxf(v00, 0.f); v01 = fmaxf(v01, 0.f);
                v10 = fmaxf(v10, 0.f); v11 = fmaxf(v11, 0.f);
            }
            if (OUT_BF) {
                __nv_bfloat16 h00 = __float2bfloat16(v00), h01 = __float2bfloat16(v01);
                __nv_bfloat16 h10 = __float2bfloat16(v10), h11 = __float2bfloat16(v11);
                __nv_bfloat16 l00 = __float2bfloat16(v00 - __bfloat162float(h00));
                __nv_bfloat16 l01 = __float2bfloat16(v01 - __bfloat162float(h01));
                __nv_bfloat16 l10 = __float2bfloat16(v10 - __bfloat162float(h10));
                __nv_bfloat16 l11 = __float2bfloat16(v11 - __bfloat162float(h11));
                *reinterpret_cast<uint32_t*>(&Ch[(size_t)r0 * N + col]) = pack_bf2(h00, h01);
                *reinterpret_cast<uint32_t*>(&Cl[(size_t)r0 * N + col]) = pack_bf2(l00, l01);
                *reinterpret_cast<uint32_t*>(&Ch[(size_t)r1 * N + col]) = pack_bf2(h10, h11);
                *reinterpret_cast<uint32_t*>(&Cl[(size_t)r1 * N + col]) = pack_bf2(l10, l11);
            } else {
                *reinterpret_cast<float2*>(&C[(size_t)r0 * N + col]) = make_float2(v00, v01);
                *reinterpret_cast<float2*>(&C[(size_t)r1 * N + col]) = make_float2(v10, v11);
            }
        }
    }
}

// ---------------- fp32 -> bf16 hi/lo splits --------------------------------
__device__ __forceinline__ void split4(const float* src, __nv_bfloat16* hi,
                                       __nv_bfloat16* lo, int i) {
    float4 v = *reinterpret_cast<const float4*>(src + i);
    __nv_bfloat16 h0 = __float2bfloat16(v.x), h1 = __float2bfloat16(v.y);
    __nv_bfloat16 h2 = __float2bfloat16(v.z), h3 = __float2bfloat16(v.w);
    __nv_bfloat16 l0 = __float2bfloat16(v.x - __bfloat162float(h0));
    __nv_bfloat16 l1 = __float2bfloat16(v.y - __bfloat162float(h1));
    __nv_bfloat16 l2 = __float2bfloat16(v.z - __bfloat162float(h2));
    __nv_bfloat16 l3 = __float2bfloat16(v.w - __bfloat162float(h3));
    *reinterpret_cast<uint2*>(&hi[i]) = make_uint2(pack_bf2(h0, h1), pack_bf2(h2, h3));
    *reinterpret_cast<uint2*>(&lo[i]) = make_uint2(pack_bf2(l0, l1), pack_bf2(l2, l3));
}

__global__ __launch_bounds__(256) void split_weights_kernel(
    const float* __restrict__ W1, __nv_bfloat16* __restrict__ w1h, __nv_bfloat16* __restrict__ w1l,
    const float* __restrict__ W2, __nv_bfloat16* __restrict__ w2h, __nv_bfloat16* __restrict__ w2l,
    const float* __restrict__ W3, __nv_bfloat16* __restrict__ w3h, __nv_bfloat16* __restrict__ w3l)
{
    const int N1 = H1_ * D_IN, N2 = H2_ * H1_, N3 = E_ * H2_;
    int i = (blockIdx.x * 256 + threadIdx.x) * 4;
    if (i < N1)                split4(W1, w1h, w1l, i);
    else if (i < N1 + N2)      split4(W2, w2h, w2l, i - N1);
    else if (i < N1 + N2 + N3) split4(W3, w3h, w3l, i - N1 - N2);
}

__global__ __launch_bounds__(256) void split_state_kernel(
    const float* __restrict__ src,
    __nv_bfloat16* __restrict__ hi, __nv_bfloat16* __restrict__ lo)
{
    int i = (blockIdx.x * 256 + threadIdx.x) * 4;
    split4(src, hi, lo, i);
}

// ============ fused shuffle: 5 x (online-softmax attention + LSTM) =========
// One block per batch, 1024 threads (32 warps). Single emb pass per iteration:
// warp w streams f-rows [w*32, w*32+32), maintaining flash-style (m, l, acc).
__global__ __launch_bounds__(1024) void shuffle_kernel(
    const float* __restrict__ emb, const int* __restrict__ length,
    const float* __restrict__ W_ih, const float* __restrict__ W_hh,
    const float* __restrict__ b_ih, const float* __restrict__ b_hh,
    float* __restrict__ out)
{
    const int b    = blockIdx.x;
    const int tid  = threadIdx.x;
    const int warp = tid >> 5, lane = tid & 31;

    __shared__ __align__(16) float s_q[H_];         // qt
    __shared__ __align__(16) float s_c[H_];         // ct
    __shared__ __align__(16) float s_x[E_];         // attended
    __shared__ __align__(16) float s_g[4 * H_];     // lstm gates
    __shared__ __align__(16) float s_part[32][E_ + 4];
    __shared__ float s_m[32], s_l[32], s_fac[32];
    __shared__ float s_invL;

    if (tid < H_) { s_q[tid] = 0.f; s_c[tid] = 0.f; }
    __syncthreads();

    const int len = length[b];
    const float* eb = emb + (size_t)b * F_ * E_;
    const float4* q4 = reinterpret_cast<const float4*>(s_q);
    const float4* x4 = reinterpret_cast<const float4*>(s_x);

    for (int it = 0; it < NSH; it++) {
        // ---- single-pass attention: logits + online softmax + attended ----
        float m = -INFINITY, l = 0.f;
        float4 a0 = make_float4(0.f, 0.f, 0.f, 0.f);
        float4 a1 = make_float4(0.f, 0.f, 0.f, 0.f);
        const float4 qv0 = q4[lane], qv1 = q4[lane + 32];
        const int fb = warp * 32;
#pragma unroll 2
        for (int ff = 0; ff < 32; ff++) {
            const int f = fb + ff;
            const float4* r4 = reinterpret_cast<const float4*>(eb + (size_t)f * E_);
            const float4 v0 = r4[lane], v1 = r4[lane + 32];
            float d = v0.x * qv0.x + v0.y * qv0.y + v0.z * qv0.z + v0.w * qv0.w;
            d = fmaf(v1.x, qv1.x, d); d = fmaf(v1.y, qv1.y, d);
            d = fmaf(v1.z, qv1.z, d); d = fmaf(v1.w, qv1.w, d);
#pragma unroll
            for (int o = 16; o; o >>= 1) d += __shfl_xor_sync(0xffffffffu, d, o);
            if (f < len) {
                const float mn = fmaxf(m, d);
                const float sc = expf(m - mn);    // 0 on first valid row
                const float p  = expf(d - mn);
                l = l * sc + p;
                a0.x = fmaf(a0.x, sc, p * v0.x); a0.y = fmaf(a0.y, sc, p * v0.y);
                a0.z = fmaf(a0.z, sc, p * v0.z); a0.w = fmaf(a0.w, sc, p * v0.w);
                a1.x = fmaf(a1.x, sc, p * v1.x); a1.y = fmaf(a1.y, sc, p * v1.y);
                a1.z = fmaf(a1.z, sc, p * v1.z); a1.w = fmaf(a1.w, sc, p * v1.w);
                m = mn;
            }
        }
        {
            float4* sp = reinterpret_cast<float4*>(s_part[warp]);
            sp[lane] = a0;
            sp[lane + 32] = a1;
            if (lane == 0) { s_m[warp] = m; s_l[warp] = l; }
        }
        __syncthreads();

        // ---- combine 32 warp-partials (warp 0) ----
        if (tid < 32) {
            const float mw = s_m[tid];
            float M = mw;
#pragma unroll
            for (int o = 16; o; o >>= 1) M = fmaxf(M, __shfl_xor_sync(0xffffffffu, M, o));
            const float fac = expf(mw - M);       // 0 if warp saw no valid rows
            s_fac[tid] = fac;
            float L = s_l[tid] * fac;
#pragma unroll
            for (int o = 16; o; o >>= 1) L += __shfl_xor_sync(0xffffffffu, L, o);
            if (tid == 0) s_invL = 1.f / L;
        }
        __syncthreads();

        if (tid < E_) {
            float s = 0.f;
#pragma unroll
            for (int w = 0; w < 32; w++) s = fmaf(s_part[w][tid], s_fac[w], s);
            s_x[tid] = s * s_invL;
        }
        __syncthreads();

        // ---- LSTM gates: warp per 32 rows ----
        {
            const float4 xv0 = x4[lane], xv1 = x4[lane + 32];
            const float4 qv0b = q4[lane], qv1b = q4[lane + 32];
            for (int j = warp * 32, je = j + 32; j < je; j++) {
                const float4* wi4 = reinterpret_cast<const float4*>(W_ih + (size_t)j * E_);
                const float4* wh4 = reinterpret_cast<const float4*>(W_hh + (size_t)j * H_);
                const float4 w0 = wi4[lane], w1 = wi4[lane + 32];
                const float4 h0 = wh4[lane], h1 = wh4[lane + 32];
                float d = w0.x * xv0.x + w0.y * xv0.y + w0.z * xv0.z + w0.w * xv0.w;
                d = fmaf(w1.x, xv1.x, d); d = fmaf(w1.y, xv1.y, d);
                d = fmaf(w1.z, xv1.z, d); d = fmaf(w1.w, xv1.w, d);
                d = fmaf(h0.x, qv0b.x, d); d = fmaf(h0.y, qv0b.y, d);
                d = fmaf(h0.z, qv0b.z, d); d = fmaf(h0.w, qv0b.w, d);
                d = fmaf(h1.x, qv1b.x, d); d = fmaf(h1.y, qv1b.y, d);
                d = fmaf(h1.z, qv1b.z, d); d = fmaf(h1.w, qv1b.w, d);
#pragma unroll
                for (int o = 16; o; o >>= 1) d += __shfl_xor_sync(0xffffffffu, d, o);
                if (lane == 0) s_g[j] = d + b_ih[j] + b_hh[j];
            }
        }
        __syncthreads();

        // ---- state update (gate order i, f, g, o) ----
        if (tid < H_) {
            const float gi = 1.f / (1.f + expf(-s_g[tid]));
            const float gf = 1.f / (1.f + expf(-s_g[H_ + tid]));
            const float gg = tanhf(s_g[2 * H_ + tid]);
            const float go = 1.f / (1.f + expf(-s_g[3 * H_ + tid]));
            const float c = gf * s_c[tid] + gi * gg;
            s_c[tid] = c;
            s_q[tid] = go * tanhf(c);
        }
        __syncthreads();
    }

    // ---- output: concat(attended, qt) ----
    if (tid < E_ + H_)
        out[b * (E_ + H_) + tid] = (tid < E_) ? s_x[tid] : s_q[tid - E_];
}

// ---------------- launch ----------------------------------------------------
extern "C" void kernel_launch(void* const* d_in, const int* in_sizes, int n_in,
                              void* d_out, int out_size)
{
    const float* state = (const float*)d_in[0];
    const int*   length= (const int*)  d_in[1];
    const float* W1    = (const float*)d_in[2];
    const float* b1    = (const float*)d_in[3];
    const float* W2    = (const float*)d_in[4];
    const float* b2    = (const float*)d_in[5];
    const float* W3    = (const float*)d_in[6];
    const float* b3    = (const float*)d_in[7];
    const float* W_ih  = (const float*)d_in[8];
    const float* W_hh  = (const float*)d_in[9];
    const float* b_ih  = (const float*)d_in[10];
    const float* b_hh  = (const float*)d_in[11];
    float* out = (float*)d_out;

    __nv_bfloat16 *sth, *stl, *h1h, *h1l, *h2h, *h2l;
    __nv_bfloat16 *w1h, *w1l, *w2h, *w2l, *w3h, *w3l;
    float *emb;
    cudaGetSymbolAddress((void**)&sth, g_sth);
    cudaGetSymbolAddress((void**)&stl, g_stl);
    cudaGetSymbolAddress((void**)&h1h, g_h1h);
    cudaGetSymbolAddress((void**)&h1l, g_h1l);
    cudaGetSymbolAddress((void**)&h2h, g_h2h);
    cudaGetSymbolAddress((void**)&h2l, g_h2l);
    cudaGetSymbolAddress((void**)&w1h, g_w1h);
    cudaGetSymbolAddress((void**)&w1l, g_w1l);
    cudaGetSymbolAddress((void**)&w2h, g_w2h);
    cudaGetSymbolAddress((void**)&w2l, g_w2l);
    cudaGetSymbolAddress((void**)&w3h, g_w3h);
    cudaGetSymbolAddress((void**)&w3l, g_w3l);
    cudaGetSymbolAddress((void**)&emb, g_emb);

    cudaFuncSetAttribute(gemm_mma_kernel<1, 1>,
                         cudaFuncAttributeMaxDynamicSharedMemorySize, GEMM_SM);
    cudaFuncSetAttribute(gemm_mma_kernel<0, 0>,
                         cudaFuncAttributeMaxDynamicSharedMemorySize, GEMM_SM);

    // 1: weight splits
    {
        int n = H1_ * D_IN + H2_ * H1_ + E_ * H2_;
        split_weights_kernel<<<n / 1024, 256>>>(W1, w1h, w1l, W2, w2h, w2l, W3, w3h, w3l);
    }
    // 2: state split
    split_state_kernel<<<(MROWS * D_IN) / 1024, 256>>>(state, sth, stl);

    // 3-5: embedder MLP on HMMA tensor cores
    {
        dim3 g1(H1_ / 128, MROWS / 128);
        gemm_mma_kernel<1, 1><<<g1, 256, GEMM_SM>>>(
            MROWS, H1_, D_IN, sth, stl, w1h, w1l, b1, nullptr, h1h, h1l);
        dim3 g2(H2_ / 128, MROWS / 128);
        gemm_mma_kernel<1, 1><<<g2, 256, GEMM_SM>>>(
            MROWS, H2_, H1_, h1h, h1l, w2h, w2l, b2, nullptr, h2h, h2l);
        dim3 g3(E_ / 128, MROWS / 128);
        gemm_mma_kernel<0, 0><<<g3, 256, GEMM_SM>>>(
            MROWS, E_, H2_, h2h, h2l, w3h, w3l, b3, emb, nullptr, nullptr);
    }

    // 6: fused shuffle loop (online-softmax attention + LSTM x5) + output
    shuffle_kernel<<<B_, 1024>>>(emb, length, W_ih, W_hh, b_ih, b_hh, out);
}